// round 6
// baseline (speedup 1.0000x reference)
#include <cuda_runtime.h>

#define S 384
#define D 512
#define H 8
#define DK 64
#define OUT_MAIN (S*S*D)   // 75497472

typedef unsigned long long ull;

__device__ __forceinline__ ull ffma2(ull a, ull b, ull c) {
    ull d;
    asm("fma.rn.f32x2 %0, %1, %2, %3;" : "=l"(d) : "l"(a), "l"(b), "l"(c));
    return d;
}
__device__ __forceinline__ ull pk2(float lo, float hi) {
    ull d; asm("mov.b64 %0, {%1, %2};" : "=l"(d) : "f"(lo), "f"(hi)); return d;
}
__device__ __forceinline__ float2 upk2(ull v) {
    float lo, hi; asm("mov.b64 {%0, %1}, %2;" : "=f"(lo), "=f"(hi) : "l"(v));
    return make_float2(lo, hi);
}

// ---------------- scratch ----------------
__device__ float g_q[S*D];
__device__ float g_k[S*D];
__device__ float g_v[S*D];
__device__ float g_M[H*DK*DK];       // Wq_h @ Wk_h^T
__device__ float g_Wvo[DK*D];        // Wv_s @ Wo
__device__ float g_bvoP[4*D];        // 4 k-partials of bv_s @ Wo
__device__ float g_wh[H*DK];         // Wk_h @ bq_h
__device__ float g_hvo2[S*H*D];      // [t][h][d], pre-scaled by 1/H
__device__ float g_attnT[S*S*H];     // [s][t][h]

// =================================================================
// K1: unified double-buffered f32x2 GEMM path
//   b <144 : qkv  (op=b/48) 64x64 tiles, K=512
//   b <152 : Wvo  (64x64 tiles over n, A=Wvs)
//   b <160 : M_h  (64x64, B transposed: C = Wq_h @ Wk_h^T)
//   b <168 : bvo partials (4 k-splits x 2 n-halves)
//   b <232 : wh (8 outputs/block, warp per output)
// 256 threads
// =================================================================
__global__ __launch_bounds__(256) void K1(
    const float* __restrict__ x,
    const float* __restrict__ Wq, const float* __restrict__ bq,
    const float* __restrict__ Wk, const float* __restrict__ bk,
    const float* __restrict__ Wv, const float* __restrict__ bv,
    const float* __restrict__ Wqh, const float* __restrict__ Wkh,
    const float* __restrict__ Wvs, const float* __restrict__ bvs,
    const float* __restrict__ bqh, const float* __restrict__ Wo)
{
    __shared__ float sm[6400];   // sA dup: 2x[16][132]=4224 ; sB: 2x[16][68]=2176
    int b = blockIdx.x;
    int tid = threadIdx.x;

    if (b < 160) {
        const float* Ap; const float* Wp; const float* biasp = 0; float* outp;
        int m0 = 0, n0 = 0, ldo; bool transB = false;
        if (b < 144) {
            int op = b / 48, r = b % 48;
            m0 = (r % 6) * 64; n0 = (r / 6) * 64;
            if (op == 0)      { Ap = x; Wp = Wq; biasp = bq; outp = g_q; }
            else if (op == 1) { Ap = x; Wp = Wk; biasp = bk; outp = g_k; }
            else              { Ap = x; Wp = Wv; biasp = bv; outp = g_v; }
            ldo = D;
        } else if (b < 152) {
            n0 = (b - 144) * 64;
            Ap = Wvs; Wp = Wo; outp = g_Wvo; ldo = D;
        } else {
            int h = b - 152;
            Ap = Wqh + h * DK * D; Wp = Wkh + h * DK * D;
            outp = g_M + h * DK * DK; ldo = DK; transB = true;
        }

        float* sA = sm;          // [2][16][132] duplicated pairs
        float* sB = sm + 4224;   // [2][16][68]

        int ma  = tid >> 2, ka4 = (tid & 3) * 4;   // A loader (and transB B loader)
        int kb  = tid >> 4, nb4 = (tid & 15) * 4;  // B loader (normal)
        int tm  = (tid >> 4) * 4, tn = (tid & 15) * 4;

        // prologue: ldg chunk 0
        float4 a4 = *(const float4*)(Ap + (m0 + ma) * D + ka4);
        float4 b4;
        if (!transB) b4 = *(const float4*)(Wp + kb * D + n0 + nb4);
        else         b4 = *(const float4*)(Wp + ma * D + ka4);

        ull acc[4][2] = {};
        for (int c = 0; c < 32; c++) {
            int buf = c & 1;
            float* sAc = sA + buf * 2112;
            float* sBc = sB + buf * 1088;
            // stage current chunk
            {
                float2 d0 = make_float2(a4.x, a4.x);
                float2 d1 = make_float2(a4.y, a4.y);
                float2 d2 = make_float2(a4.z, a4.z);
                float2 d3 = make_float2(a4.w, a4.w);
                *(float2*)&sAc[(ka4+0)*132 + 2*ma] = d0;
                *(float2*)&sAc[(ka4+1)*132 + 2*ma] = d1;
                *(float2*)&sAc[(ka4+2)*132 + 2*ma] = d2;
                *(float2*)&sAc[(ka4+3)*132 + 2*ma] = d3;
                if (!transB) {
                    *(float4*)&sBc[kb*68 + nb4] = b4;
                } else {
                    sBc[(ka4+0)*68 + ma] = b4.x;
                    sBc[(ka4+1)*68 + ma] = b4.y;
                    sBc[(ka4+2)*68 + ma] = b4.z;
                    sBc[(ka4+3)*68 + ma] = b4.w;
                }
            }
            __syncthreads();
            // prefetch next chunk
            if (c < 31) {
                int k0 = (c + 1) * 16;
                a4 = *(const float4*)(Ap + (m0 + ma) * D + k0 + ka4);
                if (!transB) b4 = *(const float4*)(Wp + (k0 + kb) * D + n0 + nb4);
                else         b4 = *(const float4*)(Wp + ma * D + k0 + ka4);
            }
            // compute on current buffer
            #pragma unroll
            for (int k2 = 0; k2 < 16; k2++) {
                ull pb0 = *(const ull*)&sBc[k2*68 + tn];
                ull pb1 = *(const ull*)&sBc[k2*68 + tn + 2];
                ull pa0 = *(const ull*)&sAc[k2*132 + 2*tm];
                ull pa1 = *(const ull*)&sAc[k2*132 + 2*tm + 2];
                ull pa2 = *(const ull*)&sAc[k2*132 + 2*tm + 4];
                ull pa3 = *(const ull*)&sAc[k2*132 + 2*tm + 6];
                acc[0][0] = ffma2(pa0, pb0, acc[0][0]); acc[0][1] = ffma2(pa0, pb1, acc[0][1]);
                acc[1][0] = ffma2(pa1, pb0, acc[1][0]); acc[1][1] = ffma2(pa1, pb1, acc[1][1]);
                acc[2][0] = ffma2(pa2, pb0, acc[2][0]); acc[2][1] = ffma2(pa2, pb1, acc[2][1]);
                acc[3][0] = ffma2(pa3, pb0, acc[3][0]); acc[3][1] = ffma2(pa3, pb1, acc[3][1]);
            }
            __syncthreads();
        }
        float4 bias4 = make_float4(0.f, 0.f, 0.f, 0.f);
        if (biasp) bias4 = *(const float4*)(biasp + n0 + tn);
        #pragma unroll
        for (int i = 0; i < 4; i++) {
            float2 lo = upk2(acc[i][0]), hi = upk2(acc[i][1]);
            float4 o4 = make_float4(lo.x + bias4.x, lo.y + bias4.y,
                                    hi.x + bias4.z, hi.y + bias4.w);
            *(float4*)(outp + (m0 + tm + i) * ldo + n0 + tn) = o4;
        }
    } else if (b < 168) {
        // ---- bvo partials: 4 k-splits x 2 n-halves ----
        int p = b - 160;
        int ks = p >> 1, nh = p & 1;
        int n = nh * 256 + tid;
        float acc = 0.f;
        int k0 = ks * 128;
        #pragma unroll 8
        for (int k = k0; k < k0 + 128; k++)
            acc += bvs[k] * Wo[k * D + n];
        g_bvoP[ks * D + n] = acc;
    } else {
        // ---- wh: warp per output, 8 per block ----
        int o = (b - 168) * 8 + (tid >> 5);
        int lane = tid & 31;
        int hh = o >> 6, ii = o & 63;
        const float4* a4p = (const float4*)(Wkh + (hh * DK + ii) * D);
        const float4* b4p = (const float4*)(bqh + hh * D);
        float acc = 0.f;
        #pragma unroll
        for (int r2 = 0; r2 < 4; r2++) {
            float4 av = a4p[lane + 32*r2], bv2 = b4p[lane + 32*r2];
            acc += av.x*bv2.x + av.y*bv2.y + av.z*bv2.z + av.w*bv2.w;
        }
        #pragma unroll
        for (int off = 16; off; off >>= 1)
            acc += __shfl_xor_sync(0xffffffffu, acc, off);
        if (lane == 0) g_wh[o] = acc;
    }
}

// =================================================================
// K2: fused { attn+softmax with inline qprime/bterm (0..191)
//             | hvo (192..575) }   256 threads
// =================================================================
__global__ __launch_bounds__(256) void K2(float* __restrict__ d_out, long long osz) {
    __shared__ float sm[8512];
    int b = blockIdx.x;
    int tid = threadIdx.x;

    if (b < 192) {
        // ---- attention rows: head h, s-tile of 16 ----
        int h = b / 24;
        int s0 = (b % 24) * 16;
        float* sKT = sm;             // [64][68]  (also holds M in prologue)
        float* sQp = sm + 4352;      // [16][68]
        float* sQ  = sm + 5440;      // [16][65]
        float* swh = sm + 6480;      // [64]
        float* sBt = sm + 6544;      // [64]

        #pragma unroll
        for (int r = 0; r < 4; r++) {
            int lin = (r * 256 + tid) * 4;
            int row = lin >> 6, col = lin & 63;
            float4 m4 = *(const float4*)(g_M + h * DK * DK + lin);
            sKT[row*68+col] = m4.x; sKT[row*68+col+1] = m4.y;
            sKT[row*68+col+2] = m4.z; sKT[row*68+col+3] = m4.w;
        }
        {
            int lin = tid * 4;
            int row = lin >> 6, col = lin & 63;
            float4 q4 = *(const float4*)(g_q + (s0 + row) * D + h * DK + col);
            sQ[row*65+col] = q4.x; sQ[row*65+col+1] = q4.y;
            sQ[row*65+col+2] = q4.z; sQ[row*65+col+3] = q4.w;
        }
        if (tid < 64) swh[tid] = g_wh[h * DK + tid];
        __syncthreads();

        {
            int sgq = tid >> 4, jg = (tid & 15) * 4;
            float a0 = 0.f, a1 = 0.f, a2 = 0.f, a3 = 0.f;
            #pragma unroll
            for (int i = 0; i < 64; i++) {
                float qv = sQ[sgq*65 + i];
                float4 m4 = *(const float4*)&sKT[i*68 + jg];
                a0 += qv*m4.x; a1 += qv*m4.y; a2 += qv*m4.z; a3 += qv*m4.w;
            }
            __syncthreads();
            sQp[sgq*68 + jg+0] = a0; sQp[sgq*68 + jg+1] = a1;
            sQp[sgq*68 + jg+2] = a2; sQp[sgq*68 + jg+3] = a3;
        }
        __syncthreads();

        int sg = tid >> 4, tg = tid & 15;
        int s = s0 + sg;
        int tt = tid & 63, kg = tid >> 6;

        float sc[24];
        for (int c = 0; c < 6; c++) {
            #pragma unroll
            for (int r = 0; r < 4; r++) {
                int k0 = kg * 16 + r * 4;
                float4 kv = *(const float4*)(g_k + (c*64 + tt) * D + h * DK + k0);
                sKT[(k0+0)*68 + tt] = kv.x;
                sKT[(k0+1)*68 + tt] = kv.y;
                sKT[(k0+2)*68 + tt] = kv.z;
                sKT[(k0+3)*68 + tt] = kv.w;
            }
            __syncthreads();
            if (tid < 64) {
                float bt = 0.f;
                #pragma unroll
                for (int k = 0; k < 64; k++) bt += sKT[k*68 + tid] * swh[k];
                sBt[tid] = bt;
            }
            ull acc0 = 0, acc1 = 0;
            #pragma unroll
            for (int k4 = 0; k4 < 16; k4++) {
                float4 q4 = *(const float4*)&sQp[sg*68 + k4*4];
                float qa[4] = {q4.x, q4.y, q4.z, q4.w};
                #pragma unroll
                for (int kk = 0; kk < 4; kk++) {
                    float4 kv = *(const float4*)&sKT[(k4*4+kk)*68 + tg*4];
                    ull kA = pk2(kv.x, kv.y), kB = pk2(kv.z, kv.w);
                    ull qp2 = pk2(qa[kk], qa[kk]);
                    acc0 = ffma2(qp2, kA, acc0);
                    acc1 = ffma2(qp2, kB, acc1);
                }
            }
            __syncthreads();
            float2 v0 = upk2(acc0), v1 = upk2(acc1);
            int tb = tg * 4;
            sc[c*4+0] = (v0.x + sBt[tb+0]) * 0.125f;
            sc[c*4+1] = (v0.y + sBt[tb+1]) * 0.125f;
            sc[c*4+2] = (v1.x + sBt[tb+2]) * 0.125f;
            sc[c*4+3] = (v1.y + sBt[tb+3]) * 0.125f;
        }

        float mx = -1e30f;
        #pragma unroll
        for (int i = 0; i < 24; i++) mx = fmaxf(mx, sc[i]);
        #pragma unroll
        for (int o = 1; o < 16; o <<= 1) mx = fmaxf(mx, __shfl_xor_sync(0xffffffffu, mx, o));
        float sum = 0.f;
        #pragma unroll
        for (int i = 0; i < 24; i++) { sc[i] = __expf(sc[i] - mx); sum += sc[i]; }
        #pragma unroll
        for (int o = 1; o < 16; o <<= 1) sum += __shfl_xor_sync(0xffffffffu, sum, o);
        float inv = 1.0f / sum;

        #pragma unroll
        for (int c = 0; c < 6; c++) {
            #pragma unroll
            for (int j = 0; j < 4; j++) {
                int t = c*64 + tg*4 + j;
                float a = sc[c*4+j] * inv;
                g_attnT[((long long)s * S + t) * H + h] = a;
                if (h == H - 1) {
                    long long oi = (long long)OUT_MAIN + (long long)s * S + t;
                    if (oi < osz) d_out[oi] = a;
                }
            }
        }
    } else {
        // ---- hvo2[t][h][:] = (vr @ Wvo + bvo) * (1/H) ----
        int p = b - 192;
        int n0 = (p & 7) * 64;
        int q = p >> 3;
        int h = q / 6, t0 = (q % 6) * 64;
        float* sV = sm;          // [64][65]
        float* sW = sm + 4160;   // [64][68]
        #pragma unroll
        for (int r = 0; r < 4; r++) {
            int lin = tid * 4 + r * 1024;
            int row = lin >> 6, col = lin & 63;
            float4 v4 = *(const float4*)(g_v + (t0 + row) * D + h * DK + col);
            sV[row*65+col] = v4.x; sV[row*65+col+1] = v4.y;
            sV[row*65+col+2] = v4.z; sV[row*65+col+3] = v4.w;
            float4 w4 = *(const float4*)(g_Wvo + row * D + n0 + col);
            *(float4*)&sW[row*68+col] = w4;
        }
        __syncthreads();
        int tl = tid >> 2, ng = (tid & 3) * 16;
        ull acc[8];
        {
            float4 s0 = make_float4(0,0,0,0), s1 = s0, s2 = s0, s3 = s0;
            #pragma unroll
            for (int part = 0; part < 4; part++) {
                const float* bp = g_bvoP + part * D + n0 + ng;
                float4 v0 = *(const float4*)bp;
                float4 v1 = *(const float4*)(bp + 4);
                float4 v2 = *(const float4*)(bp + 8);
                float4 v3 = *(const float4*)(bp + 12);
                s0.x+=v0.x; s0.y+=v0.y; s0.z+=v0.z; s0.w+=v0.w;
                s1.x+=v1.x; s1.y+=v1.y; s1.z+=v1.z; s1.w+=v1.w;
                s2.x+=v2.x; s2.y+=v2.y; s2.z+=v2.z; s2.w+=v2.w;
                s3.x+=v3.x; s3.y+=v3.y; s3.z+=v3.z; s3.w+=v3.w;
            }
            acc[0] = pk2(s0.x,s0.y); acc[1] = pk2(s0.z,s0.w);
            acc[2] = pk2(s1.x,s1.y); acc[3] = pk2(s1.z,s1.w);
            acc[4] = pk2(s2.x,s2.y); acc[5] = pk2(s2.z,s2.w);
            acc[6] = pk2(s3.x,s3.y); acc[7] = pk2(s3.z,s3.w);
        }
        #pragma unroll
        for (int i = 0; i < 64; i++) {
            float vv = sV[tl*65 + i];
            ull vp = pk2(vv, vv);
            const float* wr = &sW[i*68 + ng];
            ull w0 = *(const ull*)wr;
            ull w1 = *(const ull*)(wr + 2);
            ull w2 = *(const ull*)(wr + 4);
            ull w3 = *(const ull*)(wr + 6);
            ull w4 = *(const ull*)(wr + 8);
            ull w5 = *(const ull*)(wr + 10);
            ull w6 = *(const ull*)(wr + 12);
            ull w7 = *(const ull*)(wr + 14);
            acc[0] = ffma2(vp, w0, acc[0]);
            acc[1] = ffma2(vp, w1, acc[1]);
            acc[2] = ffma2(vp, w2, acc[2]);
            acc[3] = ffma2(vp, w3, acc[3]);
            acc[4] = ffma2(vp, w4, acc[4]);
            acc[5] = ffma2(vp, w5, acc[5]);
            acc[6] = ffma2(vp, w6, acc[6]);
            acc[7] = ffma2(vp, w7, acc[7]);
        }
        int t = t0 + tl;
        #pragma unroll
        for (int rq = 0; rq < 4; rq++) {
            float2 lo = upk2(acc[rq*2]), hi = upk2(acc[rq*2+1]);
            float4 o4 = make_float4(lo.x*0.125f, lo.y*0.125f,
                                    hi.x*0.125f, hi.y*0.125f);
            *(float4*)(g_hvo2 + (t * H + h) * D + n0 + ng + rq*4) = o4;
        }
    }
}

// =================================================================
// K4: out[s,t,:] = bo + sum_h attnT[s,t,h] * hvo2[t,h,:]  (1/H folded)
// Block = (32-s, 12-t). 256 thr = 64 d8-lanes x 4 t-quarters. f32x2.
// =================================================================
__global__ __launch_bounds__(256) void K4(float* __restrict__ d_out,
                                          const float* __restrict__ bo,
                                          long long osz) {
    __shared__ float sW[32*12*8];   // [s][t][h]
    int b = blockIdx.x;
    int s0 = (b % 12) * 32, t0 = (b / 12) * 12;
    int tid = threadIdx.x;

    #pragma unroll
    for (int r = 0; r < 3; r++) {
        int lin = r * 256 + tid;
        int st = lin >> 1, half = lin & 1;
        int s = st / 12, t = st % 12;
        *(float4*)&sW[(s*12 + t)*8 + half*4] =
            *(const float4*)(g_attnT + ((long long)(s0+s)*S + (t0+t))*H + half*4);
    }
    __syncthreads();

    int dl = (tid & 63) * 8, tq = tid >> 6;
    float4 bA = *(const float4*)(bo + dl), bB = *(const float4*)(bo + dl + 4);
    ull bop[4] = {pk2(bA.x,bA.y), pk2(bA.z,bA.w), pk2(bB.x,bB.y), pk2(bB.z,bB.w)};

    for (int i = 0; i < 3; i++) {
        int tl = i * 4 + tq;
        int t = t0 + tl;
        ull hp[8][4];
        #pragma unroll
        for (int hh = 0; hh < 8; hh++) {
            const float* p = g_hvo2 + (t * H + hh) * D + dl;
            float4 a = *(const float4*)p;
            float4 c = *(const float4*)(p + 4);
            hp[hh][0] = pk2(a.x,a.y); hp[hh][1] = pk2(a.z,a.w);
            hp[hh][2] = pk2(c.x,c.y); hp[hh][3] = pk2(c.z,c.w);
        }
        #pragma unroll
        for (int s = 0; s < 32; s++) {
            const float* wb = &sW[(s*12 + tl)*8];
            float4 wa = *(const float4*)wb;
            float4 wc = *(const float4*)(wb + 4);
            ull w0 = pk2(wa.x,wa.x), w1 = pk2(wa.y,wa.y);
            ull w2 = pk2(wa.z,wa.z), w3 = pk2(wa.w,wa.w);
            ull w4 = pk2(wc.x,wc.x), w5 = pk2(wc.y,wc.y);
            ull w6 = pk2(wc.z,wc.z), w7 = pk2(wc.w,wc.w);
            ull acc0 = bop[0], acc1 = bop[1], acc2 = bop[2], acc3 = bop[3];
            acc0 = ffma2(w0, hp[0][0], acc0); acc1 = ffma2(w0, hp[0][1], acc1);
            acc2 = ffma2(w0, hp[0][2], acc2); acc3 = ffma2(w0, hp[0][3], acc3);
            acc0 = ffma2(w1, hp[1][0], acc0); acc1 = ffma2(w1, hp[1][1], acc1);
            acc2 = ffma2(w1, hp[1][2], acc2); acc3 = ffma2(w1, hp[1][3], acc3);
            acc0 = ffma2(w2, hp[2][0], acc0); acc1 = ffma2(w2, hp[2][1], acc1);
            acc2 = ffma2(w2, hp[2][2], acc2); acc3 = ffma2(w2, hp[2][3], acc3);
            acc0 = ffma2(w3, hp[3][0], acc0); acc1 = ffma2(w3, hp[3][1], acc1);
            acc2 = ffma2(w3, hp[3][2], acc2); acc3 = ffma2(w3, hp[3][3], acc3);
            acc0 = ffma2(w4, hp[4][0], acc0); acc1 = ffma2(w4, hp[4][1], acc1);
            acc2 = ffma2(w4, hp[4][2], acc2); acc3 = ffma2(w4, hp[4][3], acc3);
            acc0 = ffma2(w5, hp[5][0], acc0); acc1 = ffma2(w5, hp[5][1], acc1);
            acc2 = ffma2(w5, hp[5][2], acc2); acc3 = ffma2(w5, hp[5][3], acc3);
            acc0 = ffma2(w6, hp[6][0], acc0); acc1 = ffma2(w6, hp[6][1], acc1);
            acc2 = ffma2(w6, hp[6][2], acc2); acc3 = ffma2(w6, hp[6][3], acc3);
            acc0 = ffma2(w7, hp[7][0], acc0); acc1 = ffma2(w7, hp[7][1], acc1);
            acc2 = ffma2(w7, hp[7][2], acc2); acc3 = ffma2(w7, hp[7][3], acc3);
            float2 r0 = upk2(acc0), r1 = upk2(acc1);
            float2 r2 = upk2(acc2), r3 = upk2(acc3);
            long long oi = ((long long)(s0 + s) * S + t) * D + dl;
            if (oi + 7 < osz) {
                __stcs((float4*)(d_out + oi),     make_float4(r0.x,r0.y,r1.x,r1.y));
                __stcs((float4*)(d_out + oi + 4), make_float4(r2.x,r2.y,r3.x,r3.y));
            }
        }
    }
}

extern "C" void kernel_launch(void* const* d_in, const int* in_sizes, int n_in,
                              void* d_out, int out_size) {
    const float* x   = (const float*)d_in[0];
    const float* Wq  = (const float*)d_in[1];
    const float* bq  = (const float*)d_in[2];
    const float* Wk  = (const float*)d_in[3];
    const float* bk  = (const float*)d_in[4];
    const float* Wv  = (const float*)d_in[5];
    const float* bv  = (const float*)d_in[6];
    const float* Wqh = (const float*)d_in[7];
    const float* bqh = (const float*)d_in[8];
    const float* Wkh = (const float*)d_in[9];
    const float* Wvs = (const float*)d_in[11];
    const float* bvs = (const float*)d_in[12];
    const float* Wo  = (const float*)d_in[13];
    const float* bo  = (const float*)d_in[14];
    float* out = (float*)d_out;
    long long osz = (long long)out_size;

    K1<<<232, 256>>>(x, Wq, bq, Wk, bk, Wv, bv, Wqh, Wkh, Wvs, bvs, bqh, Wo);
    K2<<<576, 256>>>(out, osz);
    K4<<<384, 256>>>(out, bo, osz);
}

// round 7
// speedup vs baseline: 1.0417x; 1.0417x over previous
#include <cuda_runtime.h>

#define S 384
#define D 512
#define H 8
#define DK 64
#define OUT_MAIN (S*S*D)   // 75497472

typedef unsigned long long ull;

__device__ __forceinline__ ull ffma2(ull a, ull b, ull c) {
    ull d;
    asm("fma.rn.f32x2 %0, %1, %2, %3;" : "=l"(d) : "l"(a), "l"(b), "l"(c));
    return d;
}
__device__ __forceinline__ ull pk2(float lo, float hi) {
    ull d; asm("mov.b64 %0, {%1, %2};" : "=l"(d) : "f"(lo), "f"(hi)); return d;
}
__device__ __forceinline__ float2 upk2(ull v) {
    float lo, hi; asm("mov.b64 {%0, %1}, %2;" : "=f"(lo), "=f"(hi) : "l"(v));
    return make_float2(lo, hi);
}
__device__ __forceinline__ float4 add4(float4 a, float4 b) {
    return make_float4(a.x+b.x, a.y+b.y, a.z+b.z, a.w+b.w);
}

// ---------------- scratch ----------------
// split-K partials: [ks][op][S*D] for qkv
__device__ float g_qkvP[2*3*S*D];
__device__ float g_WvoP[2*DK*D];
__device__ float g_MP[2*H*DK*DK];
__device__ float g_bvoP[4*D];        // 4 k-partials of bv_s @ Wo
__device__ float g_wh[H*DK];         // Wk_h @ bq_h
__device__ float g_hvo2[S*H*D];      // [t][h][d], pre-scaled by 1/H
__device__ float g_attnT[S*S*H];     // [s][t][h]

// =================================================================
// K1: split-K (2-way) double-buffered f32x2 GEMM path
//   b <288 : qkv   tile = b>>1 (op = tile/48), ks = b&1
//   b <304 : Wvo   nt = (b-288)>>1, ks
//   b <320 : M_h   h = (b-304)>>1, ks   (B transposed)
//   b <328 : bvo partials (4 k-splits x 2 n-halves)
//   b <336 : wh (8 outputs/block, warp per output)
// 256 threads
// =================================================================
__global__ __launch_bounds__(256) void K1(
    const float* __restrict__ x,
    const float* __restrict__ Wq, const float* __restrict__ bq,
    const float* __restrict__ Wk, const float* __restrict__ bk,
    const float* __restrict__ Wv, const float* __restrict__ bv,
    const float* __restrict__ Wqh, const float* __restrict__ Wkh,
    const float* __restrict__ Wvs, const float* __restrict__ bvs,
    const float* __restrict__ bqh, const float* __restrict__ Wo)
{
    __shared__ float sm[6400];   // sA dup: 2x[16][132]=4224 ; sB: 2x[16][68]=2176
    int b = blockIdx.x;
    int tid = threadIdx.x;

    if (b < 320) {
        const float* Ap; const float* Wp; const float* biasp = 0; float* outp;
        int m0 = 0, n0 = 0, ldo, ks; bool transB = false;
        if (b < 288) {
            int tile = b >> 1; ks = b & 1;
            int op = tile / 48, r = tile % 48;
            m0 = (r % 6) * 64; n0 = (r / 6) * 64;
            Ap = x;
            if (op == 0)      { Wp = Wq; biasp = bq; }
            else if (op == 1) { Wp = Wk; biasp = bk; }
            else              { Wp = Wv; biasp = bv; }
            if (ks) biasp = 0;             // bias only in ks=0 partial
            outp = g_qkvP + (ks * 3 + op) * S * D;
            ldo = D;
        } else if (b < 304) {
            int nt = (b - 288) >> 1; ks = (b - 288) & 1;
            n0 = nt * 64;
            Ap = Wvs; Wp = Wo; outp = g_WvoP + ks * DK * D; ldo = D;
        } else {
            int h = (b - 304) >> 1; ks = (b - 304) & 1;
            Ap = Wqh + h * DK * D; Wp = Wkh + h * DK * D;
            outp = g_MP + ks * H * DK * DK + h * DK * DK; ldo = DK; transB = true;
        }
        int kbase = ks * 256;

        float* sA = sm;          // [2][16][132] duplicated pairs
        float* sB = sm + 4224;   // [2][16][68]

        int ma  = tid >> 2, ka4 = (tid & 3) * 4;   // A loader (and transB B loader)
        int kb  = tid >> 4, nb4 = (tid & 15) * 4;  // B loader (normal)
        int tm  = (tid >> 4) * 4, tn = (tid & 15) * 4;

        // prologue: ldg chunk 0
        float4 a4 = *(const float4*)(Ap + (m0 + ma) * D + kbase + ka4);
        float4 b4;
        if (!transB) b4 = *(const float4*)(Wp + (kbase + kb) * D + n0 + nb4);
        else         b4 = *(const float4*)(Wp + ma * D + kbase + ka4);

        ull acc[4][2] = {};
        for (int c = 0; c < 16; c++) {
            int buf = c & 1;
            float* sAc = sA + buf * 2112;
            float* sBc = sB + buf * 1088;
            {
                *(float2*)&sAc[(ka4+0)*132 + 2*ma] = make_float2(a4.x, a4.x);
                *(float2*)&sAc[(ka4+1)*132 + 2*ma] = make_float2(a4.y, a4.y);
                *(float2*)&sAc[(ka4+2)*132 + 2*ma] = make_float2(a4.z, a4.z);
                *(float2*)&sAc[(ka4+3)*132 + 2*ma] = make_float2(a4.w, a4.w);
                if (!transB) {
                    *(float4*)&sBc[kb*68 + nb4] = b4;
                } else {
                    sBc[(ka4+0)*68 + ma] = b4.x;
                    sBc[(ka4+1)*68 + ma] = b4.y;
                    sBc[(ka4+2)*68 + ma] = b4.z;
                    sBc[(ka4+3)*68 + ma] = b4.w;
                }
            }
            __syncthreads();
            if (c < 15) {
                int k0 = kbase + (c + 1) * 16;
                a4 = *(const float4*)(Ap + (m0 + ma) * D + k0 + ka4);
                if (!transB) b4 = *(const float4*)(Wp + (k0 + kb) * D + n0 + nb4);
                else         b4 = *(const float4*)(Wp + ma * D + k0 + ka4);
            }
            #pragma unroll
            for (int k2 = 0; k2 < 16; k2++) {
                ull pb0 = *(const ull*)&sBc[k2*68 + tn];
                ull pb1 = *(const ull*)&sBc[k2*68 + tn + 2];
                ull pa0 = *(const ull*)&sAc[k2*132 + 2*tm];
                ull pa1 = *(const ull*)&sAc[k2*132 + 2*tm + 2];
                ull pa2 = *(const ull*)&sAc[k2*132 + 2*tm + 4];
                ull pa3 = *(const ull*)&sAc[k2*132 + 2*tm + 6];
                acc[0][0] = ffma2(pa0, pb0, acc[0][0]); acc[0][1] = ffma2(pa0, pb1, acc[0][1]);
                acc[1][0] = ffma2(pa1, pb0, acc[1][0]); acc[1][1] = ffma2(pa1, pb1, acc[1][1]);
                acc[2][0] = ffma2(pa2, pb0, acc[2][0]); acc[2][1] = ffma2(pa2, pb1, acc[2][1]);
                acc[3][0] = ffma2(pa3, pb0, acc[3][0]); acc[3][1] = ffma2(pa3, pb1, acc[3][1]);
            }
            __syncthreads();
        }
        float4 bias4 = make_float4(0.f, 0.f, 0.f, 0.f);
        if (biasp) bias4 = *(const float4*)(biasp + n0 + tn);
        #pragma unroll
        for (int i = 0; i < 4; i++) {
            float2 lo = upk2(acc[i][0]), hi = upk2(acc[i][1]);
            float4 o4 = make_float4(lo.x + bias4.x, lo.y + bias4.y,
                                    hi.x + bias4.z, hi.y + bias4.w);
            *(float4*)(outp + (m0 + tm + i) * ldo + n0 + tn) = o4;
        }
    } else if (b < 328) {
        // ---- bvo partials: 4 k-splits x 2 n-halves ----
        int p = b - 320;
        int ks = p >> 1, nh = p & 1;
        int n = nh * 256 + tid;
        float acc = 0.f;
        int k0 = ks * 128;
        #pragma unroll 8
        for (int k = k0; k < k0 + 128; k++)
            acc += bvs[k] * Wo[k * D + n];
        g_bvoP[ks * D + n] = acc;
    } else {
        // ---- wh: warp per output, 8 per block ----
        int o = (b - 328) * 8 + (tid >> 5);
        int lane = tid & 31;
        int hh = o >> 6, ii = o & 63;
        const float4* a4p = (const float4*)(Wkh + (hh * DK + ii) * D);
        const float4* b4p = (const float4*)(bqh + hh * D);
        float acc = 0.f;
        #pragma unroll
        for (int r2 = 0; r2 < 4; r2++) {
            float4 av = a4p[lane + 32*r2], bv2 = b4p[lane + 32*r2];
            acc += av.x*bv2.x + av.y*bv2.y + av.z*bv2.z + av.w*bv2.w;
        }
        #pragma unroll
        for (int off = 16; off; off >>= 1)
            acc += __shfl_xor_sync(0xffffffffu, acc, off);
        if (lane == 0) g_wh[o] = acc;
    }
}

// =================================================================
// K2: fused { attn+softmax with inline qprime/bterm (0..191)
//             | hvo (192..575) }   256 threads
// Consumers sum the split-K partials at staging time.
// =================================================================
__global__ __launch_bounds__(256) void K2(float* __restrict__ d_out, long long osz) {
    __shared__ float sm[8512];
    int b = blockIdx.x;
    int tid = threadIdx.x;

    const float* qP0 = g_qkvP;                const float* qP1 = g_qkvP + 3*S*D;
    const float* kP0 = g_qkvP + S*D;          const float* kP1 = g_qkvP + 3*S*D + S*D;
    const float* vP0 = g_qkvP + 2*S*D;        const float* vP1 = g_qkvP + 3*S*D + 2*S*D;

    if (b < 192) {
        // ---- attention rows: head h, s-tile of 16 ----
        int h = b / 24;
        int s0 = (b % 24) * 16;
        float* sKT = sm;             // [64][68]  (also holds M in prologue)
        float* sQp = sm + 4352;      // [16][68]
        float* sQ  = sm + 5440;      // [16][65]
        float* swh = sm + 6480;      // [64]
        float* sBt = sm + 6544;      // [64]

        #pragma unroll
        for (int r = 0; r < 4; r++) {
            int lin = (r * 256 + tid) * 4;
            int row = lin >> 6, col = lin & 63;
            float4 m4 = add4(*(const float4*)(g_MP + h * DK * DK + lin),
                             *(const float4*)(g_MP + H*DK*DK + h * DK * DK + lin));
            sKT[row*68+col] = m4.x; sKT[row*68+col+1] = m4.y;
            sKT[row*68+col+2] = m4.z; sKT[row*68+col+3] = m4.w;
        }
        {
            int lin = tid * 4;
            int row = lin >> 6, col = lin & 63;
            float4 q4 = add4(*(const float4*)(qP0 + (s0 + row) * D + h * DK + col),
                             *(const float4*)(qP1 + (s0 + row) * D + h * DK + col));
            sQ[row*65+col] = q4.x; sQ[row*65+col+1] = q4.y;
            sQ[row*65+col+2] = q4.z; sQ[row*65+col+3] = q4.w;
        }
        if (tid < 64) swh[tid] = g_wh[h * DK + tid];
        __syncthreads();

        {
            int sgq = tid >> 4, jg = (tid & 15) * 4;
            float a0 = 0.f, a1 = 0.f, a2 = 0.f, a3 = 0.f;
            #pragma unroll
            for (int i = 0; i < 64; i++) {
                float qv = sQ[sgq*65 + i];
                float4 m4 = *(const float4*)&sKT[i*68 + jg];
                a0 += qv*m4.x; a1 += qv*m4.y; a2 += qv*m4.z; a3 += qv*m4.w;
            }
            __syncthreads();
            sQp[sgq*68 + jg+0] = a0; sQp[sgq*68 + jg+1] = a1;
            sQp[sgq*68 + jg+2] = a2; sQp[sgq*68 + jg+3] = a3;
        }
        __syncthreads();

        int sg = tid >> 4, tg = tid & 15;
        int s = s0 + sg;
        int tt = tid & 63, kg = tid >> 6;

        float sc[24];
        for (int c = 0; c < 6; c++) {
            #pragma unroll
            for (int r = 0; r < 4; r++) {
                int k0 = kg * 16 + r * 4;
                float4 kv = add4(*(const float4*)(kP0 + (c*64 + tt) * D + h * DK + k0),
                                 *(const float4*)(kP1 + (c*64 + tt) * D + h * DK + k0));
                sKT[(k0+0)*68 + tt] = kv.x;
                sKT[(k0+1)*68 + tt] = kv.y;
                sKT[(k0+2)*68 + tt] = kv.z;
                sKT[(k0+3)*68 + tt] = kv.w;
            }
            __syncthreads();
            if (tid < 64) {
                float bt = 0.f;
                #pragma unroll
                for (int k = 0; k < 64; k++) bt += sKT[k*68 + tid] * swh[k];
                sBt[tid] = bt;
            }
            ull acc0 = 0, acc1 = 0;
            #pragma unroll
            for (int k4 = 0; k4 < 16; k4++) {
                float4 q4 = *(const float4*)&sQp[sg*68 + k4*4];
                float qa[4] = {q4.x, q4.y, q4.z, q4.w};
                #pragma unroll
                for (int kk = 0; kk < 4; kk++) {
                    float4 kv = *(const float4*)&sKT[(k4*4+kk)*68 + tg*4];
                    ull kA = pk2(kv.x, kv.y), kB = pk2(kv.z, kv.w);
                    ull qp2 = pk2(qa[kk], qa[kk]);
                    acc0 = ffma2(qp2, kA, acc0);
                    acc1 = ffma2(qp2, kB, acc1);
                }
            }
            __syncthreads();
            float2 v0 = upk2(acc0), v1 = upk2(acc1);
            int tb = tg * 4;
            sc[c*4+0] = (v0.x + sBt[tb+0]) * 0.125f;
            sc[c*4+1] = (v0.y + sBt[tb+1]) * 0.125f;
            sc[c*4+2] = (v1.x + sBt[tb+2]) * 0.125f;
            sc[c*4+3] = (v1.y + sBt[tb+3]) * 0.125f;
        }

        float mx = -1e30f;
        #pragma unroll
        for (int i = 0; i < 24; i++) mx = fmaxf(mx, sc[i]);
        #pragma unroll
        for (int o = 1; o < 16; o <<= 1) mx = fmaxf(mx, __shfl_xor_sync(0xffffffffu, mx, o));
        float sum = 0.f;
        #pragma unroll
        for (int i = 0; i < 24; i++) { sc[i] = __expf(sc[i] - mx); sum += sc[i]; }
        #pragma unroll
        for (int o = 1; o < 16; o <<= 1) sum += __shfl_xor_sync(0xffffffffu, sum, o);
        float inv = 1.0f / sum;

        #pragma unroll
        for (int c = 0; c < 6; c++) {
            #pragma unroll
            for (int j = 0; j < 4; j++) {
                int t = c*64 + tg*4 + j;
                float a = sc[c*4+j] * inv;
                g_attnT[((long long)s * S + t) * H + h] = a;
                if (h == H - 1) {
                    long long oi = (long long)OUT_MAIN + (long long)s * S + t;
                    if (oi < osz) d_out[oi] = a;
                }
            }
        }
    } else {
        // ---- hvo2[t][h][:] = (vr @ Wvo + bvo) * (1/H) ----
        int p = b - 192;
        int n0 = (p & 7) * 64;
        int q = p >> 3;
        int h = q / 6, t0 = (q % 6) * 64;
        float* sV = sm;          // [64][65]
        float* sW = sm + 4160;   // [64][68]
        #pragma unroll
        for (int r = 0; r < 4; r++) {
            int lin = tid * 4 + r * 1024;
            int row = lin >> 6, col = lin & 63;
            float4 v4 = add4(*(const float4*)(vP0 + (t0 + row) * D + h * DK + col),
                             *(const float4*)(vP1 + (t0 + row) * D + h * DK + col));
            sV[row*65+col] = v4.x; sV[row*65+col+1] = v4.y;
            sV[row*65+col+2] = v4.z; sV[row*65+col+3] = v4.w;
            float4 w4 = add4(*(const float4*)(g_WvoP + row * D + n0 + col),
                             *(const float4*)(g_WvoP + DK*D + row * D + n0 + col));
            *(float4*)&sW[row*68+col] = w4;
        }
        __syncthreads();
        int tl = tid >> 2, ng = (tid & 3) * 16;
        ull acc[8];
        {
            float4 s0 = make_float4(0,0,0,0), s1 = s0, s2 = s0, s3 = s0;
            #pragma unroll
            for (int part = 0; part < 4; part++) {
                const float* bp = g_bvoP + part * D + n0 + ng;
                s0 = add4(s0, *(const float4*)bp);
                s1 = add4(s1, *(const float4*)(bp + 4));
                s2 = add4(s2, *(const float4*)(bp + 8));
                s3 = add4(s3, *(const float4*)(bp + 12));
            }
            acc[0] = pk2(s0.x,s0.y); acc[1] = pk2(s0.z,s0.w);
            acc[2] = pk2(s1.x,s1.y); acc[3] = pk2(s1.z,s1.w);
            acc[4] = pk2(s2.x,s2.y); acc[5] = pk2(s2.z,s2.w);
            acc[6] = pk2(s3.x,s3.y); acc[7] = pk2(s3.z,s3.w);
        }
        #pragma unroll
        for (int i = 0; i < 64; i++) {
            float vv = sV[tl*65 + i];
            ull vp = pk2(vv, vv);
            const float* wr = &sW[i*68 + ng];
            ull w0 = *(const ull*)wr;
            ull w1 = *(const ull*)(wr + 2);
            ull w2 = *(const ull*)(wr + 4);
            ull w3 = *(const ull*)(wr + 6);
            ull w4 = *(const ull*)(wr + 8);
            ull w5 = *(const ull*)(wr + 10);
            ull w6 = *(const ull*)(wr + 12);
            ull w7 = *(const ull*)(wr + 14);
            acc[0] = ffma2(vp, w0, acc[0]);
            acc[1] = ffma2(vp, w1, acc[1]);
            acc[2] = ffma2(vp, w2, acc[2]);
            acc[3] = ffma2(vp, w3, acc[3]);
            acc[4] = ffma2(vp, w4, acc[4]);
            acc[5] = ffma2(vp, w5, acc[5]);
            acc[6] = ffma2(vp, w6, acc[6]);
            acc[7] = ffma2(vp, w7, acc[7]);
        }
        int t = t0 + tl;
        #pragma unroll
        for (int rq = 0; rq < 4; rq++) {
            float2 lo = upk2(acc[rq*2]), hi = upk2(acc[rq*2+1]);
            float4 o4 = make_float4(lo.x*0.125f, lo.y*0.125f,
                                    hi.x*0.125f, hi.y*0.125f);
            *(float4*)(g_hvo2 + (t * H + h) * D + n0 + ng + rq*4) = o4;
        }
    }
}

// =================================================================
// K4: out[s,t,:] = bo + sum_h attnT[s,t,h] * hvo2[t,h,:]  (1/H folded)
// Block = (32-s, 12-t). 256 thr = 64 d8-lanes x 4 t-quarters. f32x2.
// =================================================================
__global__ __launch_bounds__(256) void K4(float* __restrict__ d_out,
                                          const float* __restrict__ bo,
                                          long long osz) {
    __shared__ float sW[32*12*8];   // [s][t][h]
    int b = blockIdx.x;
    int s0 = (b % 12) * 32, t0 = (b / 12) * 12;
    int tid = threadIdx.x;

    #pragma unroll
    for (int r = 0; r < 3; r++) {
        int lin = r * 256 + tid;
        int st = lin >> 1, half = lin & 1;
        int s = st / 12, t = st % 12;
        *(float4*)&sW[(s*12 + t)*8 + half*4] =
            *(const float4*)(g_attnT + ((long long)(s0+s)*S + (t0+t))*H + half*4);
    }
    __syncthreads();

    int dl = (tid & 63) * 8, tq = tid >> 6;
    float4 bA = *(const float4*)(bo + dl), bB = *(const float4*)(bo + dl + 4);
    ull bop[4] = {pk2(bA.x,bA.y), pk2(bA.z,bA.w), pk2(bB.x,bB.y), pk2(bB.z,bB.w)};

    for (int i = 0; i < 3; i++) {
        int tl = i * 4 + tq;
        int t = t0 + tl;
        ull hp[8][4];
        #pragma unroll
        for (int hh = 0; hh < 8; hh++) {
            const float* p = g_hvo2 + (t * H + hh) * D + dl;
            float4 a = *(const float4*)p;
            float4 c = *(const float4*)(p + 4);
            hp[hh][0] = pk2(a.x,a.y); hp[hh][1] = pk2(a.z,a.w);
            hp[hh][2] = pk2(c.x,c.y); hp[hh][3] = pk2(c.z,c.w);
        }
        #pragma unroll
        for (int s = 0; s < 32; s++) {
            const float* wb = &sW[(s*12 + tl)*8];
            float4 wa = *(const float4*)wb;
            float4 wc = *(const float4*)(wb + 4);
            ull w0 = pk2(wa.x,wa.x), w1 = pk2(wa.y,wa.y);
            ull w2 = pk2(wa.z,wa.z), w3 = pk2(wa.w,wa.w);
            ull w4 = pk2(wc.x,wc.x), w5 = pk2(wc.y,wc.y);
            ull w6 = pk2(wc.z,wc.z), w7 = pk2(wc.w,wc.w);
            ull acc0 = bop[0], acc1 = bop[1], acc2 = bop[2], acc3 = bop[3];
            acc0 = ffma2(w0, hp[0][0], acc0); acc1 = ffma2(w0, hp[0][1], acc1);
            acc2 = ffma2(w0, hp[0][2], acc2); acc3 = ffma2(w0, hp[0][3], acc3);
            acc0 = ffma2(w1, hp[1][0], acc0); acc1 = ffma2(w1, hp[1][1], acc1);
            acc2 = ffma2(w1, hp[1][2], acc2); acc3 = ffma2(w1, hp[1][3], acc3);
            acc0 = ffma2(w2, hp[2][0], acc0); acc1 = ffma2(w2, hp[2][1], acc1);
            acc2 = ffma2(w2, hp[2][2], acc2); acc3 = ffma2(w2, hp[2][3], acc3);
            acc0 = ffma2(w3, hp[3][0], acc0); acc1 = ffma2(w3, hp[3][1], acc1);
            acc2 = ffma2(w3, hp[3][2], acc2); acc3 = ffma2(w3, hp[3][3], acc3);
            acc0 = ffma2(w4, hp[4][0], acc0); acc1 = ffma2(w4, hp[4][1], acc1);
            acc2 = ffma2(w4, hp[4][2], acc2); acc3 = ffma2(w4, hp[4][3], acc3);
            acc0 = ffma2(w5, hp[5][0], acc0); acc1 = ffma2(w5, hp[5][1], acc1);
            acc2 = ffma2(w5, hp[5][2], acc2); acc3 = ffma2(w5, hp[5][3], acc3);
            acc0 = ffma2(w6, hp[6][0], acc0); acc1 = ffma2(w6, hp[6][1], acc1);
            acc2 = ffma2(w6, hp[6][2], acc2); acc3 = ffma2(w6, hp[6][3], acc3);
            acc0 = ffma2(w7, hp[7][0], acc0); acc1 = ffma2(w7, hp[7][1], acc1);
            acc2 = ffma2(w7, hp[7][2], acc2); acc3 = ffma2(w7, hp[7][3], acc3);
            float2 r0 = upk2(acc0), r1 = upk2(acc1);
            float2 r2 = upk2(acc2), r3 = upk2(acc3);
            long long oi = ((long long)(s0 + s) * S + t) * D + dl;
            if (oi + 7 < osz) {
                __stcs((float4*)(d_out + oi),     make_float4(r0.x,r0.y,r1.x,r1.y));
                __stcs((float4*)(d_out + oi + 4), make_float4(r2.x,r2.y,r3.x,r3.y));
            }
        }
    }
}

extern "C" void kernel_launch(void* const* d_in, const int* in_sizes, int n_in,
                              void* d_out, int out_size) {
    const float* x   = (const float*)d_in[0];
    const float* Wq  = (const float*)d_in[1];
    const float* bq  = (const float*)d_in[2];
    const float* Wk  = (const float*)d_in[3];
    const float* bk  = (const float*)d_in[4];
    const float* Wv  = (const float*)d_in[5];
    const float* bv  = (const float*)d_in[6];
    const float* Wqh = (const float*)d_in[7];
    const float* bqh = (const float*)d_in[8];
    const float* Wkh = (const float*)d_in[9];
    const float* Wvs = (const float*)d_in[11];
    const float* bvs = (const float*)d_in[12];
    const float* Wo  = (const float*)d_in[13];
    const float* bo  = (const float*)d_in[14];
    float* out = (float*)d_out;
    long long osz = (long long)out_size;

    K1<<<336, 256>>>(x, Wq, bq, Wk, bk, Wv, bv, Wqh, Wkh, Wvs, bvs, bqh, Wo);
    K2<<<576, 256>>>(out, osz);
    K4<<<384, 256>>>(out, bo, osz);
}

// round 8
// speedup vs baseline: 1.1397x; 1.0941x over previous
#include <cuda_runtime.h>

#define S 384
#define D 512
#define H 8
#define DK 64
#define OUT_MAIN (S*S*D)   // 75497472

typedef unsigned long long ull;

__device__ __forceinline__ ull ffma2(ull a, ull b, ull c) {
    ull d;
    asm("fma.rn.f32x2 %0, %1, %2, %3;" : "=l"(d) : "l"(a), "l"(b), "l"(c));
    return d;
}
__device__ __forceinline__ ull pk2(float lo, float hi) {
    ull d; asm("mov.b64 %0, {%1, %2};" : "=l"(d) : "f"(lo), "f"(hi)); return d;
}
__device__ __forceinline__ float2 upk2(ull v) {
    float lo, hi; asm("mov.b64 {%0, %1}, %2;" : "=f"(lo), "=f"(hi) : "l"(v));
    return make_float2(lo, hi);
}
__device__ __forceinline__ float4 add4(float4 a, float4 b) {
    return make_float4(a.x+b.x, a.y+b.y, a.z+b.z, a.w+b.w);
}

// ---------------- scratch ----------------
__device__ float g_qkvP[2*3*S*D];    // split-K partials [ks][op][S*D]
__device__ float g_WvoP[2*DK*D];
__device__ float g_MP[2*H*DK*DK];
__device__ float g_bvoP[4*D];
__device__ float g_qkv[3*S*D];       // reduced: q | k | v
__device__ float g_M[H*DK*DK];
__device__ float g_Wvo[DK*D];
__device__ float g_bvo[D];
__device__ float g_wh[H*DK];
__device__ float g_hvo2[S*H*D];      // [t][h][d], pre-scaled by 1/H
__device__ float g_attnT[S*S*H];     // [s][t][h]

// =================================================================
// K1: split-K (2-way) double-buffered f32x2 GEMM path (as R7)
// =================================================================
__global__ __launch_bounds__(256) void K1(
    const float* __restrict__ x,
    const float* __restrict__ Wq, const float* __restrict__ bq,
    const float* __restrict__ Wk, const float* __restrict__ bk,
    const float* __restrict__ Wv, const float* __restrict__ bv,
    const float* __restrict__ Wqh, const float* __restrict__ Wkh,
    const float* __restrict__ Wvs, const float* __restrict__ bvs,
    const float* __restrict__ bqh, const float* __restrict__ Wo)
{
    __shared__ float sm[6400];
    int b = blockIdx.x;
    int tid = threadIdx.x;

    if (b < 320) {
        const float* Ap; const float* Wp; const float* biasp = 0; float* outp;
        int m0 = 0, n0 = 0, ldo, ks; bool transB = false;
        if (b < 288) {
            int tile = b >> 1; ks = b & 1;
            int op = tile / 48, r = tile % 48;
            m0 = (r % 6) * 64; n0 = (r / 6) * 64;
            Ap = x;
            if (op == 0)      { Wp = Wq; biasp = bq; }
            else if (op == 1) { Wp = Wk; biasp = bk; }
            else              { Wp = Wv; biasp = bv; }
            if (ks) biasp = 0;
            outp = g_qkvP + (ks * 3 + op) * S * D;
            ldo = D;
        } else if (b < 304) {
            int nt = (b - 288) >> 1; ks = (b - 288) & 1;
            n0 = nt * 64;
            Ap = Wvs; Wp = Wo; outp = g_WvoP + ks * DK * D; ldo = D;
        } else {
            int h = (b - 304) >> 1; ks = (b - 304) & 1;
            Ap = Wqh + h * DK * D; Wp = Wkh + h * DK * D;
            outp = g_MP + ks * H * DK * DK + h * DK * DK; ldo = DK; transB = true;
        }
        int kbase = ks * 256;

        float* sA = sm;          // [2][16][132] duplicated pairs
        float* sB = sm + 4224;   // [2][16][68]

        int ma  = tid >> 2, ka4 = (tid & 3) * 4;
        int kb  = tid >> 4, nb4 = (tid & 15) * 4;
        int tm  = (tid >> 4) * 4, tn = (tid & 15) * 4;

        float4 a4 = *(const float4*)(Ap + (m0 + ma) * D + kbase + ka4);
        float4 b4;
        if (!transB) b4 = *(const float4*)(Wp + (kbase + kb) * D + n0 + nb4);
        else         b4 = *(const float4*)(Wp + ma * D + kbase + ka4);

        ull acc[4][2] = {};
        for (int c = 0; c < 16; c++) {
            int buf = c & 1;
            float* sAc = sA + buf * 2112;
            float* sBc = sB + buf * 1088;
            {
                *(float2*)&sAc[(ka4+0)*132 + 2*ma] = make_float2(a4.x, a4.x);
                *(float2*)&sAc[(ka4+1)*132 + 2*ma] = make_float2(a4.y, a4.y);
                *(float2*)&sAc[(ka4+2)*132 + 2*ma] = make_float2(a4.z, a4.z);
                *(float2*)&sAc[(ka4+3)*132 + 2*ma] = make_float2(a4.w, a4.w);
                if (!transB) {
                    *(float4*)&sBc[kb*68 + nb4] = b4;
                } else {
                    sBc[(ka4+0)*68 + ma] = b4.x;
                    sBc[(ka4+1)*68 + ma] = b4.y;
                    sBc[(ka4+2)*68 + ma] = b4.z;
                    sBc[(ka4+3)*68 + ma] = b4.w;
                }
            }
            __syncthreads();
            if (c < 15) {
                int k0 = kbase + (c + 1) * 16;
                a4 = *(const float4*)(Ap + (m0 + ma) * D + k0 + ka4);
                if (!transB) b4 = *(const float4*)(Wp + (k0 + kb) * D + n0 + nb4);
                else         b4 = *(const float4*)(Wp + ma * D + k0 + ka4);
            }
            #pragma unroll
            for (int k2 = 0; k2 < 16; k2++) {
                ull pb0 = *(const ull*)&sBc[k2*68 + tn];
                ull pb1 = *(const ull*)&sBc[k2*68 + tn + 2];
                ull pa0 = *(const ull*)&sAc[k2*132 + 2*tm];
                ull pa1 = *(const ull*)&sAc[k2*132 + 2*tm + 2];
                ull pa2 = *(const ull*)&sAc[k2*132 + 2*tm + 4];
                ull pa3 = *(const ull*)&sAc[k2*132 + 2*tm + 6];
                acc[0][0] = ffma2(pa0, pb0, acc[0][0]); acc[0][1] = ffma2(pa0, pb1, acc[0][1]);
                acc[1][0] = ffma2(pa1, pb0, acc[1][0]); acc[1][1] = ffma2(pa1, pb1, acc[1][1]);
                acc[2][0] = ffma2(pa2, pb0, acc[2][0]); acc[2][1] = ffma2(pa2, pb1, acc[2][1]);
                acc[3][0] = ffma2(pa3, pb0, acc[3][0]); acc[3][1] = ffma2(pa3, pb1, acc[3][1]);
            }
            __syncthreads();
        }
        float4 bias4 = make_float4(0.f, 0.f, 0.f, 0.f);
        if (biasp) bias4 = *(const float4*)(biasp + n0 + tn);
        #pragma unroll
        for (int i = 0; i < 4; i++) {
            float2 lo = upk2(acc[i][0]), hi = upk2(acc[i][1]);
            float4 o4 = make_float4(lo.x + bias4.x, lo.y + bias4.y,
                                    hi.x + bias4.z, hi.y + bias4.w);
            *(float4*)(outp + (m0 + tm + i) * ldo + n0 + tn) = o4;
        }
    } else if (b < 328) {
        int p = b - 320;
        int ks = p >> 1, nh = p & 1;
        int n = nh * 256 + tid;
        float acc = 0.f;
        int k0 = ks * 128;
        #pragma unroll 8
        for (int k = k0; k < k0 + 128; k++)
            acc += bvs[k] * Wo[k * D + n];
        g_bvoP[ks * D + n] = acc;
    } else {
        int o = (b - 328) * 8 + (tid >> 5);
        int lane = tid & 31;
        int hh = o >> 6, ii = o & 63;
        const float4* a4p = (const float4*)(Wkh + (hh * DK + ii) * D);
        const float4* b4p = (const float4*)(bqh + hh * D);
        float acc = 0.f;
        #pragma unroll
        for (int r2 = 0; r2 < 4; r2++) {
            float4 av = a4p[lane + 32*r2], bv2 = b4p[lane + 32*r2];
            acc += av.x*bv2.x + av.y*bv2.y + av.z*bv2.z + av.w*bv2.w;
        }
        #pragma unroll
        for (int off = 16; off; off >>= 1)
            acc += __shfl_xor_sync(0xffffffffu, acc, off);
        if (lane == 0) g_wh[o] = acc;
    }
}

// =================================================================
// K1r: reduce split-K partials once
// =================================================================
__global__ __launch_bounds__(256) void K1r() {
    int idx = blockIdx.x * 256 + threadIdx.x;
    if (idx < 147456) {
        float4 a = ((const float4*)g_qkvP)[idx];
        float4 b = ((const float4*)g_qkvP)[idx + 147456];
        ((float4*)g_qkv)[idx] = add4(a, b);
    } else if (idx < 155648) {
        int i = idx - 147456;
        float4 a = ((const float4*)g_MP)[i];
        float4 b = ((const float4*)g_MP)[i + 8192];
        ((float4*)g_M)[i] = add4(a, b);
    } else if (idx < 163840) {
        int i = idx - 155648;
        float4 a = ((const float4*)g_WvoP)[i];
        float4 b = ((const float4*)g_WvoP)[i + 8192];
        ((float4*)g_Wvo)[i] = add4(a, b);
    } else if (idx < 163968) {
        int i = idx - 163840;
        float4 s = make_float4(0.f, 0.f, 0.f, 0.f);
        #pragma unroll
        for (int p = 0; p < 4; p++)
            s = add4(s, ((const float4*)g_bvoP)[p * 128 + i]);
        ((float4*)g_bvo)[i] = s;
    }
}

// =================================================================
// K2: fused { attn+softmax with inline qprime/bterm (0..191)
//             | hvo (192..575) }   256 threads  (R5 form)
// =================================================================
__global__ __launch_bounds__(256) void K2(float* __restrict__ d_out, long long osz) {
    __shared__ float sm[8512];
    int b = blockIdx.x;
    int tid = threadIdx.x;

    const float* gq = g_qkv;
    const float* gk = g_qkv + S*D;
    const float* gv = g_qkv + 2*S*D;

    if (b < 192) {
        int h = b / 24;
        int s0 = (b % 24) * 16;
        float* sKT = sm;             // [64][68]
        float* sQp = sm + 4352;      // [16][68]
        float* sQ  = sm + 5440;      // [16][65]
        float* swh = sm + 6480;      // [64]
        float* sBt = sm + 6544;      // [64]

        #pragma unroll
        for (int r = 0; r < 4; r++) {
            int lin = (r * 256 + tid) * 4;
            int row = lin >> 6, col = lin & 63;
            float4 m4 = *(const float4*)(g_M + h * DK * DK + lin);
            sKT[row*68+col] = m4.x; sKT[row*68+col+1] = m4.y;
            sKT[row*68+col+2] = m4.z; sKT[row*68+col+3] = m4.w;
        }
        {
            int lin = tid * 4;
            int row = lin >> 6, col = lin & 63;
            float4 q4 = *(const float4*)(gq + (s0 + row) * D + h * DK + col);
            sQ[row*65+col] = q4.x; sQ[row*65+col+1] = q4.y;
            sQ[row*65+col+2] = q4.z; sQ[row*65+col+3] = q4.w;
        }
        if (tid < 64) swh[tid] = g_wh[h * DK + tid];
        __syncthreads();

        {
            int sgq = tid >> 4, jg = (tid & 15) * 4;
            float a0 = 0.f, a1 = 0.f, a2 = 0.f, a3 = 0.f;
            #pragma unroll
            for (int i = 0; i < 64; i++) {
                float qv = sQ[sgq*65 + i];
                float4 m4 = *(const float4*)&sKT[i*68 + jg];
                a0 += qv*m4.x; a1 += qv*m4.y; a2 += qv*m4.z; a3 += qv*m4.w;
            }
            __syncthreads();
            sQp[sgq*68 + jg+0] = a0; sQp[sgq*68 + jg+1] = a1;
            sQp[sgq*68 + jg+2] = a2; sQp[sgq*68 + jg+3] = a3;
        }
        __syncthreads();

        int sg = tid >> 4, tg = tid & 15;
        int s = s0 + sg;
        int tt = tid & 63, kg = tid >> 6;

        float sc[24];
        for (int c = 0; c < 6; c++) {
            #pragma unroll
            for (int r = 0; r < 4; r++) {
                int k0 = kg * 16 + r * 4;
                float4 kv = *(const float4*)(gk + (c*64 + tt) * D + h * DK + k0);
                sKT[(k0+0)*68 + tt] = kv.x;
                sKT[(k0+1)*68 + tt] = kv.y;
                sKT[(k0+2)*68 + tt] = kv.z;
                sKT[(k0+3)*68 + tt] = kv.w;
            }
            __syncthreads();
            if (tid < 64) {
                float bt = 0.f;
                #pragma unroll
                for (int k = 0; k < 64; k++) bt += sKT[k*68 + tid] * swh[k];
                sBt[tid] = bt;
            }
            ull acc0 = 0, acc1 = 0;
            #pragma unroll
            for (int k4 = 0; k4 < 16; k4++) {
                float4 q4 = *(const float4*)&sQp[sg*68 + k4*4];
                float qa[4] = {q4.x, q4.y, q4.z, q4.w};
                #pragma unroll
                for (int kk = 0; kk < 4; kk++) {
                    float4 kv = *(const float4*)&sKT[(k4*4+kk)*68 + tg*4];
                    ull kA = pk2(kv.x, kv.y), kB = pk2(kv.z, kv.w);
                    ull qp2 = pk2(qa[kk], qa[kk]);
                    acc0 = ffma2(qp2, kA, acc0);
                    acc1 = ffma2(qp2, kB, acc1);
                }
            }
            __syncthreads();
            float2 v0 = upk2(acc0), v1 = upk2(acc1);
            int tb = tg * 4;
            sc[c*4+0] = (v0.x + sBt[tb+0]) * 0.125f;
            sc[c*4+1] = (v0.y + sBt[tb+1]) * 0.125f;
            sc[c*4+2] = (v1.x + sBt[tb+2]) * 0.125f;
            sc[c*4+3] = (v1.y + sBt[tb+3]) * 0.125f;
        }

        float mx = -1e30f;
        #pragma unroll
        for (int i = 0; i < 24; i++) mx = fmaxf(mx, sc[i]);
        #pragma unroll
        for (int o = 1; o < 16; o <<= 1) mx = fmaxf(mx, __shfl_xor_sync(0xffffffffu, mx, o));
        float sum = 0.f;
        #pragma unroll
        for (int i = 0; i < 24; i++) { sc[i] = __expf(sc[i] - mx); sum += sc[i]; }
        #pragma unroll
        for (int o = 1; o < 16; o <<= 1) sum += __shfl_xor_sync(0xffffffffu, sum, o);
        float inv = 1.0f / sum;

        #pragma unroll
        for (int c = 0; c < 6; c++) {
            #pragma unroll
            for (int j = 0; j < 4; j++) {
                int t = c*64 + tg*4 + j;
                float a = sc[c*4+j] * inv;
                g_attnT[((long long)s * S + t) * H + h] = a;
                if (h == H - 1) {
                    long long oi = (long long)OUT_MAIN + (long long)s * S + t;
                    if (oi < osz) d_out[oi] = a;
                }
            }
        }
    } else {
        // ---- hvo2[t][h][:] = (vr @ Wvo + bvo) * (1/H) ----
        int p = b - 192;
        int n0 = (p & 7) * 64;
        int q = p >> 3;
        int h = q / 6, t0 = (q % 6) * 64;
        float* sV = sm;          // [64][65]
        float* sW = sm + 4160;   // [64][68]
        #pragma unroll
        for (int r = 0; r < 4; r++) {
            int lin = tid * 4 + r * 1024;
            int row = lin >> 6, col = lin & 63;
            float4 v4 = *(const float4*)(gv + (t0 + row) * D + h * DK + col);
            sV[row*65+col] = v4.x; sV[row*65+col+1] = v4.y;
            sV[row*65+col+2] = v4.z; sV[row*65+col+3] = v4.w;
            float4 w4 = *(const float4*)(g_Wvo + row * D + n0 + col);
            *(float4*)&sW[row*68+col] = w4;
        }
        __syncthreads();
        int tl = tid >> 2, ng = (tid & 3) * 16;
        ull acc[8];
        {
            float4 b0 = *(const float4*)(g_bvo + n0 + ng);
            float4 b1 = *(const float4*)(g_bvo + n0 + ng + 4);
            float4 b2 = *(const float4*)(g_bvo + n0 + ng + 8);
            float4 b3 = *(const float4*)(g_bvo + n0 + ng + 12);
            acc[0] = pk2(b0.x,b0.y); acc[1] = pk2(b0.z,b0.w);
            acc[2] = pk2(b1.x,b1.y); acc[3] = pk2(b1.z,b1.w);
            acc[4] = pk2(b2.x,b2.y); acc[5] = pk2(b2.z,b2.w);
            acc[6] = pk2(b3.x,b3.y); acc[7] = pk2(b3.z,b3.w);
        }
        #pragma unroll
        for (int i = 0; i < 64; i++) {
            float vv = sV[tl*65 + i];
            ull vp = pk2(vv, vv);
            const float* wr = &sW[i*68 + ng];
            acc[0] = ffma2(vp, *(const ull*)wr,        acc[0]);
            acc[1] = ffma2(vp, *(const ull*)(wr + 2),  acc[1]);
            acc[2] = ffma2(vp, *(const ull*)(wr + 4),  acc[2]);
            acc[3] = ffma2(vp, *(const ull*)(wr + 6),  acc[3]);
            acc[4] = ffma2(vp, *(const ull*)(wr + 8),  acc[4]);
            acc[5] = ffma2(vp, *(const ull*)(wr + 10), acc[5]);
            acc[6] = ffma2(vp, *(const ull*)(wr + 12), acc[6]);
            acc[7] = ffma2(vp, *(const ull*)(wr + 14), acc[7]);
        }
        int t = t0 + tl;
        #pragma unroll
        for (int rq = 0; rq < 4; rq++) {
            float2 lo = upk2(acc[rq*2]), hi = upk2(acc[rq*2+1]);
            float4 o4 = make_float4(lo.x*0.125f, lo.y*0.125f,
                                    hi.x*0.125f, hi.y*0.125f);
            *(float4*)(g_hvo2 + (t * H + h) * D + n0 + ng + rq*4) = o4;
        }
    }
}

// =================================================================
// K4: out[s,t,:] = bo + sum_h attnT[s,t,h] * hvo2[t,h,:]
// Block = (4-t tile via tq, 96-s range). 256 thr = 64 d8 x 4 tq.
// hvo held in registers for the whole block.
// =================================================================
__global__ __launch_bounds__(256) void K4(float* __restrict__ d_out,
                                          const float* __restrict__ bo,
                                          long long osz) {
    __shared__ float sA[32*4*8];   // [s][t][h]
    int b = blockIdx.x;
    int t0 = (b % 96) * 4;
    int s0 = (b / 96) * 96;
    int tid = threadIdx.x;
    int dl = (tid & 63) * 8, tq = tid >> 6;
    int t = t0 + tq;

    ull hp[8][4];
    #pragma unroll
    for (int hh = 0; hh < 8; hh++) {
        const float* p = g_hvo2 + (t * H + hh) * D + dl;
        float4 a = *(const float4*)p;
        float4 c = *(const float4*)(p + 4);
        hp[hh][0] = pk2(a.x,a.y); hp[hh][1] = pk2(a.z,a.w);
        hp[hh][2] = pk2(c.x,c.y); hp[hh][3] = pk2(c.z,c.w);
    }
    float4 bA = *(const float4*)(bo + dl), bB = *(const float4*)(bo + dl + 4);
    ull bop[4] = {pk2(bA.x,bA.y), pk2(bA.z,bA.w), pk2(bB.x,bB.y), pk2(bB.z,bB.w)};

    for (int ch = 0; ch < 3; ch++) {
        int sb = s0 + ch * 32;
        {   // stage attn [32 s][4 t][8 h]: 256 float4
            int sload = tid >> 3, rem = tid & 7;
            int tt2 = rem >> 1, half = rem & 1;
            *(float4*)&sA[sload*32 + tt2*8 + half*4] =
                *(const float4*)(g_attnT + ((long long)(sb+sload)*S + t0+tt2)*H + half*4);
        }
        __syncthreads();
        long long oi = ((long long)sb * S + t) * D + dl;
        #pragma unroll 4
        for (int s = 0; s < 32; s++) {
            const float* wb = &sA[s*32 + tq*8];
            float4 wa = *(const float4*)wb;
            float4 wc = *(const float4*)(wb + 4);
            ull w0 = pk2(wa.x,wa.x), w1 = pk2(wa.y,wa.y);
            ull w2 = pk2(wa.z,wa.z), w3 = pk2(wa.w,wa.w);
            ull w4 = pk2(wc.x,wc.x), w5 = pk2(wc.y,wc.y);
            ull w6 = pk2(wc.z,wc.z), w7 = pk2(wc.w,wc.w);
            ull acc0 = bop[0], acc1 = bop[1], acc2 = bop[2], acc3 = bop[3];
            acc0 = ffma2(w0, hp[0][0], acc0); acc1 = ffma2(w0, hp[0][1], acc1);
            acc2 = ffma2(w0, hp[0][2], acc2); acc3 = ffma2(w0, hp[0][3], acc3);
            acc0 = ffma2(w1, hp[1][0], acc0); acc1 = ffma2(w1, hp[1][1], acc1);
            acc2 = ffma2(w1, hp[1][2], acc2); acc3 = ffma2(w1, hp[1][3], acc3);
            acc0 = ffma2(w2, hp[2][0], acc0); acc1 = ffma2(w2, hp[2][1], acc1);
            acc2 = ffma2(w2, hp[2][2], acc2); acc3 = ffma2(w2, hp[2][3], acc3);
            acc0 = ffma2(w3, hp[3][0], acc0); acc1 = ffma2(w3, hp[3][1], acc1);
            acc2 = ffma2(w3, hp[3][2], acc2); acc3 = ffma2(w3, hp[3][3], acc3);
            acc0 = ffma2(w4, hp[4][0], acc0); acc1 = ffma2(w4, hp[4][1], acc1);
            acc2 = ffma2(w4, hp[4][2], acc2); acc3 = ffma2(w4, hp[4][3], acc3);
            acc0 = ffma2(w5, hp[5][0], acc0); acc1 = ffma2(w5, hp[5][1], acc1);
            acc2 = ffma2(w5, hp[5][2], acc2); acc3 = ffma2(w5, hp[5][3], acc3);
            acc0 = ffma2(w6, hp[6][0], acc0); acc1 = ffma2(w6, hp[6][1], acc1);
            acc2 = ffma2(w6, hp[6][2], acc2); acc3 = ffma2(w6, hp[6][3], acc3);
            acc0 = ffma2(w7, hp[7][0], acc0); acc1 = ffma2(w7, hp[7][1], acc1);
            acc2 = ffma2(w7, hp[7][2], acc2); acc3 = ffma2(w7, hp[7][3], acc3);
            float2 r0 = upk2(acc0), r1 = upk2(acc1);
            float2 r2 = upk2(acc2), r3 = upk2(acc3);
            if (oi + 7 < osz) {
                __stcs((float4*)(d_out + oi),     make_float4(r0.x,r0.y,r1.x,r1.y));
                __stcs((float4*)(d_out + oi + 4), make_float4(r2.x,r2.y,r3.x,r3.y));
            }
            oi += (long long)S * D;
        }
        __syncthreads();
    }
}

extern "C" void kernel_launch(void* const* d_in, const int* in_sizes, int n_in,
                              void* d_out, int out_size) {
    const float* x   = (const float*)d_in[0];
    const float* Wq  = (const float*)d_in[1];
    const float* bq  = (const float*)d_in[2];
    const float* Wk  = (const float*)d_in[3];
    const float* bk  = (const float*)d_in[4];
    const float* Wv  = (const float*)d_in[5];
    const float* bv  = (const float*)d_in[6];
    const float* Wqh = (const float*)d_in[7];
    const float* bqh = (const float*)d_in[8];
    const float* Wkh = (const float*)d_in[9];
    const float* Wvs = (const float*)d_in[11];
    const float* bvs = (const float*)d_in[12];
    const float* Wo  = (const float*)d_in[13];
    const float* bo  = (const float*)d_in[14];
    float* out = (float*)d_out;
    long long osz = (long long)out_size;

    K1 <<<336, 256>>>(x, Wq, bq, Wk, bk, Wv, bv, Wqh, Wkh, Wvs, bvs, bqh, Wo);
    K1r<<<641, 256>>>();
    K2 <<<576, 256>>>(out, osz);
    K4 <<<384, 256>>>(out, bo, osz);
}

// round 9
// speedup vs baseline: 1.3963x; 1.2252x over previous
#include <cuda_runtime.h>

#define S 384
#define D 512
#define H 8
#define DK 64
#define OUT_MAIN (S*S*D)   // 75497472

typedef unsigned long long ull;

__device__ __forceinline__ ull ffma2(ull a, ull b, ull c) {
    ull d;
    asm("fma.rn.f32x2 %0, %1, %2, %3;" : "=l"(d) : "l"(a), "l"(b), "l"(c));
    return d;
}
__device__ __forceinline__ ull pk2(float lo, float hi) {
    ull d; asm("mov.b64 %0, {%1, %2};" : "=l"(d) : "f"(lo), "f"(hi)); return d;
}
__device__ __forceinline__ float2 upk2(ull v) {
    float lo, hi; asm("mov.b64 {%0, %1}, %2;" : "=f"(lo), "=f"(hi) : "l"(v));
    return make_float2(lo, hi);
}
__device__ __forceinline__ float4 add4(float4 a, float4 b) {
    return make_float4(a.x+b.x, a.y+b.y, a.z+b.z, a.w+b.w);
}

// ---------------- scratch ----------------
__device__ float g_qkvP[4*3*S*D];    // split-K partials [ks][op][S*D]
__device__ float g_WvoP[2*DK*D];
__device__ float g_MP[2*H*DK*DK];
__device__ float g_bvoP[4*D];
__device__ float g_qkv[3*S*D];       // reduced: q | k | v
__device__ float g_M[H*DK*DK];
__device__ float g_Wvo[DK*D];
__device__ float g_bvo[D];
__device__ float g_wh[H*DK];
__device__ float g_hvo2[S*H*D];      // [t][h][d], pre-scaled by 1/H
__device__ float g_attnT[S*S*H];     // [s][t][h]

// =================================================================
// K1: split-K double-buffered f32x2 GEMM path
//   b <576 : qkv   tile = b>>2 (op = tile/48), ks = b&3, K=128 each
//   b <592 : Wvo   split-2, K=256 each
//   b <608 : M_h   split-2 (B transposed)
//   b <616 : bvo partials | b <624 : wh
// =================================================================
__global__ __launch_bounds__(256) void K1(
    const float* __restrict__ x,
    const float* __restrict__ Wq, const float* __restrict__ bq,
    const float* __restrict__ Wk, const float* __restrict__ bk,
    const float* __restrict__ Wv, const float* __restrict__ bv,
    const float* __restrict__ Wqh, const float* __restrict__ Wkh,
    const float* __restrict__ Wvs, const float* __restrict__ bvs,
    const float* __restrict__ bqh, const float* __restrict__ Wo)
{
    __shared__ float sm[6400];
    int b = blockIdx.x;
    int tid = threadIdx.x;

    if (b < 608) {
        const float* Ap; const float* Wp; const float* biasp = 0; float* outp;
        int m0 = 0, n0 = 0, ldo, kbase, nchunks; bool transB = false;
        if (b < 576) {
            int tile = b >> 2; int ks = b & 3;
            int op = tile / 48, r = tile % 48;
            m0 = (r % 6) * 64; n0 = (r / 6) * 64;
            Ap = x;
            if (op == 0)      { Wp = Wq; biasp = bq; }
            else if (op == 1) { Wp = Wk; biasp = bk; }
            else              { Wp = Wv; biasp = bv; }
            if (ks) biasp = 0;
            outp = g_qkvP + (ks * 3 + op) * S * D;
            ldo = D; kbase = ks * 128; nchunks = 8;
        } else if (b < 592) {
            int nt = (b - 576) >> 1; int ks = (b - 576) & 1;
            n0 = nt * 64;
            Ap = Wvs; Wp = Wo; outp = g_WvoP + ks * DK * D; ldo = D;
            kbase = ks * 256; nchunks = 16;
        } else {
            int h = (b - 592) >> 1; int ks = (b - 592) & 1;
            Ap = Wqh + h * DK * D; Wp = Wkh + h * DK * D;
            outp = g_MP + ks * H * DK * DK + h * DK * DK; ldo = DK; transB = true;
            kbase = ks * 256; nchunks = 16;
        }

        float* sA = sm;          // [2][16][132] duplicated pairs
        float* sB = sm + 4224;   // [2][16][68]

        int ma  = tid >> 2, ka4 = (tid & 3) * 4;
        int kb  = tid >> 4, nb4 = (tid & 15) * 4;
        int tm  = (tid >> 4) * 4, tn = (tid & 15) * 4;

        float4 a4 = *(const float4*)(Ap + (m0 + ma) * D + kbase + ka4);
        float4 b4;
        if (!transB) b4 = *(const float4*)(Wp + (kbase + kb) * D + n0 + nb4);
        else         b4 = *(const float4*)(Wp + ma * D + kbase + ka4);

        ull acc[4][2] = {};
        for (int c = 0; c < nchunks; c++) {
            int buf = c & 1;
            float* sAc = sA + buf * 2112;
            float* sBc = sB + buf * 1088;
            {
                *(float2*)&sAc[(ka4+0)*132 + 2*ma] = make_float2(a4.x, a4.x);
                *(float2*)&sAc[(ka4+1)*132 + 2*ma] = make_float2(a4.y, a4.y);
                *(float2*)&sAc[(ka4+2)*132 + 2*ma] = make_float2(a4.z, a4.z);
                *(float2*)&sAc[(ka4+3)*132 + 2*ma] = make_float2(a4.w, a4.w);
                if (!transB) {
                    *(float4*)&sBc[kb*68 + nb4] = b4;
                } else {
                    sBc[(ka4+0)*68 + ma] = b4.x;
                    sBc[(ka4+1)*68 + ma] = b4.y;
                    sBc[(ka4+2)*68 + ma] = b4.z;
                    sBc[(ka4+3)*68 + ma] = b4.w;
                }
            }
            __syncthreads();
            if (c < nchunks - 1) {
                int k0 = kbase + (c + 1) * 16;
                a4 = *(const float4*)(Ap + (m0 + ma) * D + k0 + ka4);
                if (!transB) b4 = *(const float4*)(Wp + (k0 + kb) * D + n0 + nb4);
                else         b4 = *(const float4*)(Wp + ma * D + k0 + ka4);
            }
            #pragma unroll
            for (int k2 = 0; k2 < 16; k2++) {
                ull pb0 = *(const ull*)&sBc[k2*68 + tn];
                ull pb1 = *(const ull*)&sBc[k2*68 + tn + 2];
                ull pa0 = *(const ull*)&sAc[k2*132 + 2*tm];
                ull pa1 = *(const ull*)&sAc[k2*132 + 2*tm + 2];
                ull pa2 = *(const ull*)&sAc[k2*132 + 2*tm + 4];
                ull pa3 = *(const ull*)&sAc[k2*132 + 2*tm + 6];
                acc[0][0] = ffma2(pa0, pb0, acc[0][0]); acc[0][1] = ffma2(pa0, pb1, acc[0][1]);
                acc[1][0] = ffma2(pa1, pb0, acc[1][0]); acc[1][1] = ffma2(pa1, pb1, acc[1][1]);
                acc[2][0] = ffma2(pa2, pb0, acc[2][0]); acc[2][1] = ffma2(pa2, pb1, acc[2][1]);
                acc[3][0] = ffma2(pa3, pb0, acc[3][0]); acc[3][1] = ffma2(pa3, pb1, acc[3][1]);
            }
            __syncthreads();
        }
        float4 bias4 = make_float4(0.f, 0.f, 0.f, 0.f);
        if (biasp) bias4 = *(const float4*)(biasp + n0 + tn);
        #pragma unroll
        for (int i = 0; i < 4; i++) {
            float2 lo = upk2(acc[i][0]), hi = upk2(acc[i][1]);
            float4 o4 = make_float4(lo.x + bias4.x, lo.y + bias4.y,
                                    hi.x + bias4.z, hi.y + bias4.w);
            *(float4*)(outp + (m0 + tm + i) * ldo + n0 + tn) = o4;
        }
    } else if (b < 616) {
        int p = b - 608;
        int ks = p >> 1, nh = p & 1;
        int n = nh * 256 + tid;
        float acc = 0.f;
        int k0 = ks * 128;
        #pragma unroll 8
        for (int k = k0; k < k0 + 128; k++)
            acc += bvs[k] * Wo[k * D + n];
        g_bvoP[ks * D + n] = acc;
    } else {
        int o = (b - 616) * 8 + (tid >> 5);
        int lane = tid & 31;
        int hh = o >> 6, ii = o & 63;
        const float4* a4p = (const float4*)(Wkh + (hh * DK + ii) * D);
        const float4* b4p = (const float4*)(bqh + hh * D);
        float acc = 0.f;
        #pragma unroll
        for (int r2 = 0; r2 < 4; r2++) {
            float4 av = a4p[lane + 32*r2], bv2 = b4p[lane + 32*r2];
            acc += av.x*bv2.x + av.y*bv2.y + av.z*bv2.z + av.w*bv2.w;
        }
        #pragma unroll
        for (int off = 16; off; off >>= 1)
            acc += __shfl_xor_sync(0xffffffffu, acc, off);
        if (lane == 0) g_wh[o] = acc;
    }
}

// =================================================================
// K1r: reduce split-K partials once
// =================================================================
__global__ __launch_bounds__(256) void K1r() {
    int idx = blockIdx.x * 256 + threadIdx.x;
    if (idx < 147456) {
        float4 s = ((const float4*)g_qkvP)[idx];
        #pragma unroll
        for (int p = 1; p < 4; p++)
            s = add4(s, ((const float4*)g_qkvP)[idx + p * 147456]);
        ((float4*)g_qkv)[idx] = s;
    } else if (idx < 155648) {
        int i = idx - 147456;
        float4 a = ((const float4*)g_MP)[i];
        float4 b = ((const float4*)g_MP)[i + 8192];
        ((float4*)g_M)[i] = add4(a, b);
    } else if (idx < 163840) {
        int i = idx - 155648;
        float4 a = ((const float4*)g_WvoP)[i];
        float4 b = ((const float4*)g_WvoP)[i + 8192];
        ((float4*)g_Wvo)[i] = add4(a, b);
    } else if (idx < 163968) {
        int i = idx - 163840;
        float4 s = make_float4(0.f, 0.f, 0.f, 0.f);
        #pragma unroll
        for (int p = 0; p < 4; p++)
            s = add4(s, ((const float4*)g_bvoP)[p * 128 + i]);
        ((float4*)g_bvo)[i] = s;
    }
}

// =================================================================
// K2: fused { attn+softmax with inline qprime/bterm (0..191)
//             | hvo (192..575) }   256 threads
// =================================================================
__global__ __launch_bounds__(256) void K2(float* __restrict__ d_out, long long osz) {
    __shared__ float sm[8512];
    int b = blockIdx.x;
    int tid = threadIdx.x;

    const float* gq = g_qkv;
    const float* gk = g_qkv + S*D;
    const float* gv = g_qkv + 2*S*D;

    if (b < 192) {
        int h = b / 24;
        int s0 = (b % 24) * 16;
        float* sKT = sm;             // [64][68]
        float* sQp = sm + 4352;      // [16][68]
        float* sQ  = sm + 5440;      // [16][65]
        float* swh = sm + 6480;      // [64]
        float* sBt = sm + 6544;      // [64]

        #pragma unroll
        for (int r = 0; r < 4; r++) {
            int lin = (r * 256 + tid) * 4;
            int row = lin >> 6, col = lin & 63;
            float4 m4 = *(const float4*)(g_M + h * DK * DK + lin);
            sKT[row*68+col] = m4.x; sKT[row*68+col+1] = m4.y;
            sKT[row*68+col+2] = m4.z; sKT[row*68+col+3] = m4.w;
        }
        {
            int lin = tid * 4;
            int row = lin >> 6, col = lin & 63;
            float4 q4 = *(const float4*)(gq + (s0 + row) * D + h * DK + col);
            sQ[row*65+col] = q4.x; sQ[row*65+col+1] = q4.y;
            sQ[row*65+col+2] = q4.z; sQ[row*65+col+3] = q4.w;
        }
        if (tid < 64) swh[tid] = g_wh[h * DK + tid];
        __syncthreads();

        {
            int sgq = tid >> 4, jg = (tid & 15) * 4;
            float a0 = 0.f, a1 = 0.f, a2 = 0.f, a3 = 0.f;
            #pragma unroll
            for (int i = 0; i < 64; i++) {
                float qv = sQ[sgq*65 + i];
                float4 m4 = *(const float4*)&sKT[i*68 + jg];
                a0 += qv*m4.x; a1 += qv*m4.y; a2 += qv*m4.z; a3 += qv*m4.w;
            }
            __syncthreads();
            sQp[sgq*68 + jg+0] = a0; sQp[sgq*68 + jg+1] = a1;
            sQp[sgq*68 + jg+2] = a2; sQp[sgq*68 + jg+3] = a3;
        }
        __syncthreads();

        int sg = tid >> 4, tg = tid & 15;
        int s = s0 + sg;
        int tt = tid & 63, kg = tid >> 6;

        float sc[24];
        for (int c = 0; c < 6; c++) {
            #pragma unroll
            for (int r = 0; r < 4; r++) {
                int k0 = kg * 16 + r * 4;
                float4 kv = *(const float4*)(gk + (c*64 + tt) * D + h * DK + k0);
                sKT[(k0+0)*68 + tt] = kv.x;
                sKT[(k0+1)*68 + tt] = kv.y;
                sKT[(k0+2)*68 + tt] = kv.z;
                sKT[(k0+3)*68 + tt] = kv.w;
            }
            __syncthreads();
            if (tid < 64) {
                float bt = 0.f;
                #pragma unroll
                for (int k = 0; k < 64; k++) bt += sKT[k*68 + tid] * swh[k];
                sBt[tid] = bt;
            }
            ull acc0 = 0, acc1 = 0;
            #pragma unroll
            for (int k4 = 0; k4 < 16; k4++) {
                float4 q4 = *(const float4*)&sQp[sg*68 + k4*4];
                float qa[4] = {q4.x, q4.y, q4.z, q4.w};
                #pragma unroll
                for (int kk = 0; kk < 4; kk++) {
                    float4 kv = *(const float4*)&sKT[(k4*4+kk)*68 + tg*4];
                    ull kA = pk2(kv.x, kv.y), kB = pk2(kv.z, kv.w);
                    ull qp2 = pk2(qa[kk], qa[kk]);
                    acc0 = ffma2(qp2, kA, acc0);
                    acc1 = ffma2(qp2, kB, acc1);
                }
            }
            __syncthreads();
            float2 v0 = upk2(acc0), v1 = upk2(acc1);
            int tb = tg * 4;
            sc[c*4+0] = (v0.x + sBt[tb+0]) * 0.125f;
            sc[c*4+1] = (v0.y + sBt[tb+1]) * 0.125f;
            sc[c*4+2] = (v1.x + sBt[tb+2]) * 0.125f;
            sc[c*4+3] = (v1.y + sBt[tb+3]) * 0.125f;
        }

        float mx = -1e30f;
        #pragma unroll
        for (int i = 0; i < 24; i++) mx = fmaxf(mx, sc[i]);
        #pragma unroll
        for (int o = 1; o < 16; o <<= 1) mx = fmaxf(mx, __shfl_xor_sync(0xffffffffu, mx, o));
        float sum = 0.f;
        #pragma unroll
        for (int i = 0; i < 24; i++) { sc[i] = __expf(sc[i] - mx); sum += sc[i]; }
        #pragma unroll
        for (int o = 1; o < 16; o <<= 1) sum += __shfl_xor_sync(0xffffffffu, sum, o);
        float inv = 1.0f / sum;

        #pragma unroll
        for (int c = 0; c < 6; c++) {
            #pragma unroll
            for (int j = 0; j < 4; j++) {
                int t = c*64 + tg*4 + j;
                float a = sc[c*4+j] * inv;
                g_attnT[((long long)s * S + t) * H + h] = a;
                if (h == H - 1) {
                    long long oi = (long long)OUT_MAIN + (long long)s * S + t;
                    if (oi < osz) d_out[oi] = a;
                }
            }
        }
    } else {
        // ---- hvo2[t][h][:] = (vr @ Wvo + bvo) * (1/H) ----
        int p = b - 192;
        int n0 = (p & 7) * 64;
        int q = p >> 3;
        int h = q / 6, t0 = (q % 6) * 64;
        float* sV = sm;          // [64][65]
        float* sW = sm + 4160;   // [64][68]
        #pragma unroll
        for (int r = 0; r < 4; r++) {
            int lin = tid * 4 + r * 1024;
            int row = lin >> 6, col = lin & 63;
            float4 v4 = *(const float4*)(gv + (t0 + row) * D + h * DK + col);
            sV[row*65+col] = v4.x; sV[row*65+col+1] = v4.y;
            sV[row*65+col+2] = v4.z; sV[row*65+col+3] = v4.w;
            float4 w4 = *(const float4*)(g_Wvo + row * D + n0 + col);
            *(float4*)&sW[row*68+col] = w4;
        }
        __syncthreads();
        int tl = tid >> 2, ng = (tid & 3) * 16;
        ull acc[8];
        {
            float4 b0 = *(const float4*)(g_bvo + n0 + ng);
            float4 b1 = *(const float4*)(g_bvo + n0 + ng + 4);
            float4 b2 = *(const float4*)(g_bvo + n0 + ng + 8);
            float4 b3 = *(const float4*)(g_bvo + n0 + ng + 12);
            acc[0] = pk2(b0.x,b0.y); acc[1] = pk2(b0.z,b0.w);
            acc[2] = pk2(b1.x,b1.y); acc[3] = pk2(b1.z,b1.w);
            acc[4] = pk2(b2.x,b2.y); acc[5] = pk2(b2.z,b2.w);
            acc[6] = pk2(b3.x,b3.y); acc[7] = pk2(b3.z,b3.w);
        }
        #pragma unroll
        for (int i = 0; i < 64; i++) {
            float vv = sV[tl*65 + i];
            ull vp = pk2(vv, vv);
            const float* wr = &sW[i*68 + ng];
            acc[0] = ffma2(vp, *(const ull*)wr,        acc[0]);
            acc[1] = ffma2(vp, *(const ull*)(wr + 2),  acc[1]);
            acc[2] = ffma2(vp, *(const ull*)(wr + 4),  acc[2]);
            acc[3] = ffma2(vp, *(const ull*)(wr + 6),  acc[3]);
            acc[4] = ffma2(vp, *(const ull*)(wr + 8),  acc[4]);
            acc[5] = ffma2(vp, *(const ull*)(wr + 10), acc[5]);
            acc[6] = ffma2(vp, *(const ull*)(wr + 12), acc[6]);
            acc[7] = ffma2(vp, *(const ull*)(wr + 14), acc[7]);
        }
        int t = t0 + tl;
        #pragma unroll
        for (int rq = 0; rq < 4; rq++) {
            float2 lo = upk2(acc[rq*2]), hi = upk2(acc[rq*2+1]);
            float4 o4 = make_float4(lo.x*0.125f, lo.y*0.125f,
                                    hi.x*0.125f, hi.y*0.125f);
            *(float4*)(g_hvo2 + (t * H + h) * D + n0 + ng + rq*4) = o4;
        }
    }
}

// =================================================================
// K4: out[s,t,:] = bo + sum_h attnT[s,t,h] * hvo2[t,h,:]
// Block = (2-t tile, 96-s range). 256 thr = 128 d4 x 2 tq. 3 CTAs/SM.
// =================================================================
__global__ __launch_bounds__(256, 3) void K4(float* __restrict__ d_out,
                                             const float* __restrict__ bo,
                                             long long osz) {
    __shared__ float sA[32*2*8];   // [s][t][h] = 512 floats
    int b = blockIdx.x;
    int t0 = (b % 192) * 2;
    int s0 = (b / 192) * 96;
    int tid = threadIdx.x;
    int dl = (tid & 127) * 4, tq = tid >> 7;
    int t = t0 + tq;

    ull hp[8][2];
    #pragma unroll
    for (int hh = 0; hh < 8; hh++) {
        float4 a = *(const float4*)(g_hvo2 + (t * H + hh) * D + dl);
        hp[hh][0] = pk2(a.x, a.y); hp[hh][1] = pk2(a.z, a.w);
    }
    float4 bA = *(const float4*)(bo + dl);
    ull bop0 = pk2(bA.x, bA.y), bop1 = pk2(bA.z, bA.w);

    for (int ch = 0; ch < 3; ch++) {
        int sb = s0 + ch * 32;
        if (tid < 128) {    // stage attn [32 s][2 t][8 h] = 128 float4
            int s = tid >> 2, rem = tid & 3;
            int tt2 = rem >> 1, half = rem & 1;
            *(float4*)&sA[s*16 + tt2*8 + half*4] =
                *(const float4*)(g_attnT + ((long long)(sb+s)*S + t0+tt2)*H + half*4);
        }
        __syncthreads();
        long long oi = ((long long)sb * S + t) * D + dl;
        #pragma unroll 4
        for (int s = 0; s < 32; s++) {
            const float* wb = &sA[s*16 + tq*8];
            float4 wa = *(const float4*)wb;
            float4 wc = *(const float4*)(wb + 4);
            ull w0 = pk2(wa.x,wa.x), w1 = pk2(wa.y,wa.y);
            ull w2 = pk2(wa.z,wa.z), w3 = pk2(wa.w,wa.w);
            ull w4 = pk2(wc.x,wc.x), w5 = pk2(wc.y,wc.y);
            ull w6 = pk2(wc.z,wc.z), w7 = pk2(wc.w,wc.w);
            ull acc0 = bop0, acc1 = bop1;
            acc0 = ffma2(w0, hp[0][0], acc0); acc1 = ffma2(w0, hp[0][1], acc1);
            acc0 = ffma2(w1, hp[1][0], acc0); acc1 = ffma2(w1, hp[1][1], acc1);
            acc0 = ffma2(w2, hp[2][0], acc0); acc1 = ffma2(w2, hp[2][1], acc1);
            acc0 = ffma2(w3, hp[3][0], acc0); acc1 = ffma2(w3, hp[3][1], acc1);
            acc0 = ffma2(w4, hp[4][0], acc0); acc1 = ffma2(w4, hp[4][1], acc1);
            acc0 = ffma2(w5, hp[5][0], acc0); acc1 = ffma2(w5, hp[5][1], acc1);
            acc0 = ffma2(w6, hp[6][0], acc0); acc1 = ffma2(w6, hp[6][1], acc1);
            acc0 = ffma2(w7, hp[7][0], acc0); acc1 = ffma2(w7, hp[7][1], acc1);
            float2 r0 = upk2(acc0), r1 = upk2(acc1);
            if (oi + 3 < osz)
                __stcs((float4*)(d_out + oi), make_float4(r0.x, r0.y, r1.x, r1.y));
            oi += (long long)S * D;
        }
        __syncthreads();
    }
}

extern "C" void kernel_launch(void* const* d_in, const int* in_sizes, int n_in,
                              void* d_out, int out_size) {
    const float* x   = (const float*)d_in[0];
    const float* Wq  = (const float*)d_in[1];
    const float* bq  = (const float*)d_in[2];
    const float* Wk  = (const float*)d_in[3];
    const float* bk  = (const float*)d_in[4];
    const float* Wv  = (const float*)d_in[5];
    const float* bv  = (const float*)d_in[6];
    const float* Wqh = (const float*)d_in[7];
    const float* bqh = (const float*)d_in[8];
    const float* Wkh = (const float*)d_in[9];
    const float* Wvs = (const float*)d_in[11];
    const float* bvs = (const float*)d_in[12];
    const float* Wo  = (const float*)d_in[13];
    const float* bo  = (const float*)d_in[14];
    float* out = (float*)d_out;
    long long osz = (long long)out_size;

    K1 <<<624, 256>>>(x, Wq, bq, Wk, bk, Wv, bv, Wqh, Wkh, Wvs, bvs, bqh, Wo);
    K1r<<<641, 256>>>();
    K2 <<<576, 256>>>(out, osz);
    K4 <<<768, 256>>>(out, bo, osz);
}

// round 10
// speedup vs baseline: 1.4093x; 1.0093x over previous
#include <cuda_runtime.h>

#define S 384
#define D 512
#define H 8
#define DK 64
#define OUT_MAIN (S*S*D)   // 75497472

typedef unsigned long long ull;

__device__ __forceinline__ ull ffma2(ull a, ull b, ull c) {
    ull d;
    asm("fma.rn.f32x2 %0, %1, %2, %3;" : "=l"(d) : "l"(a), "l"(b), "l"(c));
    return d;
}
__device__ __forceinline__ ull pk2(float lo, float hi) {
    ull d; asm("mov.b64 %0, {%1, %2};" : "=l"(d) : "f"(lo), "f"(hi)); return d;
}
__device__ __forceinline__ float2 upk2(ull v) {
    float lo, hi; asm("mov.b64 {%0, %1}, %2;" : "=f"(lo), "=f"(hi) : "l"(v));
    return make_float2(lo, hi);
}
__device__ __forceinline__ float4 add4(float4 a, float4 b) {
    return make_float4(a.x+b.x, a.y+b.y, a.z+b.z, a.w+b.w);
}

// ---------------- scratch ----------------
__device__ float g_qkvP[4*3*S*D];    // split-K partials [ks][op][S*D]
__device__ float g_WvoP[2*DK*D];
__device__ float g_MP[2*H*DK*DK];
__device__ float g_bvoP[4*D];
__device__ float g_qkv[3*S*D];       // reduced: q | k | v
__device__ float g_M[H*DK*DK];
__device__ float g_Wvo[DK*D];
__device__ float g_bvo[D];
__device__ float g_wh[H*DK];
__device__ float g_hvo2[S*H*D];      // [t][h][d], pre-scaled by 1/H
__device__ float g_attnT[S*S*H];     // [s][t][h]

// =================================================================
// K1: split-K double-buffered f32x2 GEMM path
// =================================================================
__global__ __launch_bounds__(256) void K1(
    const float* __restrict__ x,
    const float* __restrict__ Wq, const float* __restrict__ bq,
    const float* __restrict__ Wk, const float* __restrict__ bk,
    const float* __restrict__ Wv, const float* __restrict__ bv,
    const float* __restrict__ Wqh, const float* __restrict__ Wkh,
    const float* __restrict__ Wvs, const float* __restrict__ bvs,
    const float* __restrict__ bqh, const float* __restrict__ Wo)
{
    __shared__ float sm[6400];
    int b = blockIdx.x;
    int tid = threadIdx.x;

    if (b < 608) {
        const float* Ap; const float* Wp; const float* biasp = 0; float* outp;
        int m0 = 0, n0 = 0, ldo, kbase, nchunks; bool transB = false;
        if (b < 576) {
            int tile = b >> 2; int ks = b & 3;
            int op = tile / 48, r = tile % 48;
            m0 = (r % 6) * 64; n0 = (r / 6) * 64;
            Ap = x;
            if (op == 0)      { Wp = Wq; biasp = bq; }
            else if (op == 1) { Wp = Wk; biasp = bk; }
            else              { Wp = Wv; biasp = bv; }
            if (ks) biasp = 0;
            outp = g_qkvP + (ks * 3 + op) * S * D;
            ldo = D; kbase = ks * 128; nchunks = 8;
        } else if (b < 592) {
            int nt = (b - 576) >> 1; int ks = (b - 576) & 1;
            n0 = nt * 64;
            Ap = Wvs; Wp = Wo; outp = g_WvoP + ks * DK * D; ldo = D;
            kbase = ks * 256; nchunks = 16;
        } else {
            int h = (b - 592) >> 1; int ks = (b - 592) & 1;
            Ap = Wqh + h * DK * D; Wp = Wkh + h * DK * D;
            outp = g_MP + ks * H * DK * DK + h * DK * DK; ldo = DK; transB = true;
            kbase = ks * 256; nchunks = 16;
        }

        float* sA = sm;          // [2][16][132] duplicated pairs
        float* sB = sm + 4224;   // [2][16][68]

        int ma  = tid >> 2, ka4 = (tid & 3) * 4;
        int kb  = tid >> 4, nb4 = (tid & 15) * 4;
        int tm  = (tid >> 4) * 4, tn = (tid & 15) * 4;

        float4 a4 = *(const float4*)(Ap + (m0 + ma) * D + kbase + ka4);
        float4 b4;
        if (!transB) b4 = *(const float4*)(Wp + (kbase + kb) * D + n0 + nb4);
        else         b4 = *(const float4*)(Wp + ma * D + kbase + ka4);

        ull acc[4][2] = {};
        for (int c = 0; c < nchunks; c++) {
            int buf = c & 1;
            float* sAc = sA + buf * 2112;
            float* sBc = sB + buf * 1088;
            {
                *(float2*)&sAc[(ka4+0)*132 + 2*ma] = make_float2(a4.x, a4.x);
                *(float2*)&sAc[(ka4+1)*132 + 2*ma] = make_float2(a4.y, a4.y);
                *(float2*)&sAc[(ka4+2)*132 + 2*ma] = make_float2(a4.z, a4.z);
                *(float2*)&sAc[(ka4+3)*132 + 2*ma] = make_float2(a4.w, a4.w);
                if (!transB) {
                    *(float4*)&sBc[kb*68 + nb4] = b4;
                } else {
                    sBc[(ka4+0)*68 + ma] = b4.x;
                    sBc[(ka4+1)*68 + ma] = b4.y;
                    sBc[(ka4+2)*68 + ma] = b4.z;
                    sBc[(ka4+3)*68 + ma] = b4.w;
                }
            }
            __syncthreads();
            if (c < nchunks - 1) {
                int k0 = kbase + (c + 1) * 16;
                a4 = *(const float4*)(Ap + (m0 + ma) * D + k0 + ka4);
                if (!transB) b4 = *(const float4*)(Wp + (k0 + kb) * D + n0 + nb4);
                else         b4 = *(const float4*)(Wp + ma * D + k0 + ka4);
            }
            #pragma unroll
            for (int k2 = 0; k2 < 16; k2++) {
                ull pb0 = *(const ull*)&sBc[k2*68 + tn];
                ull pb1 = *(const ull*)&sBc[k2*68 + tn + 2];
                ull pa0 = *(const ull*)&sAc[k2*132 + 2*tm];
                ull pa1 = *(const ull*)&sAc[k2*132 + 2*tm + 2];
                ull pa2 = *(const ull*)&sAc[k2*132 + 2*tm + 4];
                ull pa3 = *(const ull*)&sAc[k2*132 + 2*tm + 6];
                acc[0][0] = ffma2(pa0, pb0, acc[0][0]); acc[0][1] = ffma2(pa0, pb1, acc[0][1]);
                acc[1][0] = ffma2(pa1, pb0, acc[1][0]); acc[1][1] = ffma2(pa1, pb1, acc[1][1]);
                acc[2][0] = ffma2(pa2, pb0, acc[2][0]); acc[2][1] = ffma2(pa2, pb1, acc[2][1]);
                acc[3][0] = ffma2(pa3, pb0, acc[3][0]); acc[3][1] = ffma2(pa3, pb1, acc[3][1]);
            }
            __syncthreads();
        }
        float4 bias4 = make_float4(0.f, 0.f, 0.f, 0.f);
        if (biasp) bias4 = *(const float4*)(biasp + n0 + tn);
        #pragma unroll
        for (int i = 0; i < 4; i++) {
            float2 lo = upk2(acc[i][0]), hi = upk2(acc[i][1]);
            float4 o4 = make_float4(lo.x + bias4.x, lo.y + bias4.y,
                                    hi.x + bias4.z, hi.y + bias4.w);
            *(float4*)(outp + (m0 + tm + i) * ldo + n0 + tn) = o4;
        }
    } else if (b < 616) {
        int p = b - 608;
        int ks = p >> 1, nh = p & 1;
        int n = nh * 256 + tid;
        float acc = 0.f;
        int k0 = ks * 128;
        #pragma unroll 8
        for (int k = k0; k < k0 + 128; k++)
            acc += bvs[k] * Wo[k * D + n];
        g_bvoP[ks * D + n] = acc;
    } else {
        int o = (b - 616) * 8 + (tid >> 5);
        int lane = tid & 31;
        int hh = o >> 6, ii = o & 63;
        const float4* a4p = (const float4*)(Wkh + (hh * DK + ii) * D);
        const float4* b4p = (const float4*)(bqh + hh * D);
        float acc = 0.f;
        #pragma unroll
        for (int r2 = 0; r2 < 4; r2++) {
            float4 av = a4p[lane + 32*r2], bv2 = b4p[lane + 32*r2];
            acc += av.x*bv2.x + av.y*bv2.y + av.z*bv2.z + av.w*bv2.w;
        }
        #pragma unroll
        for (int off = 16; off; off >>= 1)
            acc += __shfl_xor_sync(0xffffffffu, acc, off);
        if (lane == 0) g_wh[o] = acc;
    }
}

// =================================================================
// K1r: reduce split-K partials once
// =================================================================
__global__ __launch_bounds__(256) void K1r() {
    int idx = blockIdx.x * 256 + threadIdx.x;
    if (idx < 147456) {
        float4 s = ((const float4*)g_qkvP)[idx];
        #pragma unroll
        for (int p = 1; p < 4; p++)
            s = add4(s, ((const float4*)g_qkvP)[idx + p * 147456]);
        ((float4*)g_qkv)[idx] = s;
    } else if (idx < 155648) {
        int i = idx - 147456;
        float4 a = ((const float4*)g_MP)[i];
        float4 b = ((const float4*)g_MP)[i + 8192];
        ((float4*)g_M)[i] = add4(a, b);
    } else if (idx < 163840) {
        int i = idx - 155648;
        float4 a = ((const float4*)g_WvoP)[i];
        float4 b = ((const float4*)g_WvoP)[i + 8192];
        ((float4*)g_Wvo)[i] = add4(a, b);
    } else if (idx < 163968) {
        int i = idx - 163840;
        float4 s = make_float4(0.f, 0.f, 0.f, 0.f);
        #pragma unroll
        for (int p = 0; p < 4; p++)
            s = add4(s, ((const float4*)g_bvoP)[p * 128 + i]);
        ((float4*)g_bvo)[i] = s;
    }
}

// =================================================================
// K2: fused { attn+softmax with inline qprime/bterm (0..191)
//             | hvo (192..575) }   256 threads
// =================================================================
__global__ __launch_bounds__(256) void K2(float* __restrict__ d_out, long long osz) {
    __shared__ float sm[8512];
    int b = blockIdx.x;
    int tid = threadIdx.x;

    const float* gq = g_qkv;
    const float* gk = g_qkv + S*D;
    const float* gv = g_qkv + 2*S*D;

    if (b < 192) {
        int h = b / 24;
        int s0 = (b % 24) * 16;
        float* sKT = sm;             // [64][68]
        float* sQp = sm + 4352;      // [16][68]
        float* sQ  = sm + 5440;      // [16][65]
        float* swh = sm + 6480;      // [64]
        float* sBt = sm + 6544;      // [64]

        #pragma unroll
        for (int r = 0; r < 4; r++) {
            int lin = (r * 256 + tid) * 4;
            int row = lin >> 6, col = lin & 63;
            float4 m4 = *(const float4*)(g_M + h * DK * DK + lin);
            sKT[row*68+col] = m4.x; sKT[row*68+col+1] = m4.y;
            sKT[row*68+col+2] = m4.z; sKT[row*68+col+3] = m4.w;
        }
        {
            int lin = tid * 4;
            int row = lin >> 6, col = lin & 63;
            float4 q4 = *(const float4*)(gq + (s0 + row) * D + h * DK + col);
            sQ[row*65+col] = q4.x; sQ[row*65+col+1] = q4.y;
            sQ[row*65+col+2] = q4.z; sQ[row*65+col+3] = q4.w;
        }
        if (tid < 64) swh[tid] = g_wh[h * DK + tid];
        __syncthreads();

        {
            int sgq = tid >> 4, jg = (tid & 15) * 4;
            float a0 = 0.f, a1 = 0.f, a2 = 0.f, a3 = 0.f;
            #pragma unroll
            for (int i = 0; i < 64; i++) {
                float qv = sQ[sgq*65 + i];
                float4 m4 = *(const float4*)&sKT[i*68 + jg];
                a0 += qv*m4.x; a1 += qv*m4.y; a2 += qv*m4.z; a3 += qv*m4.w;
            }
            __syncthreads();
            sQp[sgq*68 + jg+0] = a0; sQp[sgq*68 + jg+1] = a1;
            sQp[sgq*68 + jg+2] = a2; sQp[sgq*68 + jg+3] = a3;
        }
        __syncthreads();

        int sg = tid >> 4, tg = tid & 15;
        int s = s0 + sg;
        int tt = tid & 63, kg = tid >> 6;

        float sc[24];
        for (int c = 0; c < 6; c++) {
            #pragma unroll
            for (int r = 0; r < 4; r++) {
                int k0 = kg * 16 + r * 4;
                float4 kv = *(const float4*)(gk + (c*64 + tt) * D + h * DK + k0);
                sKT[(k0+0)*68 + tt] = kv.x;
                sKT[(k0+1)*68 + tt] = kv.y;
                sKT[(k0+2)*68 + tt] = kv.z;
                sKT[(k0+3)*68 + tt] = kv.w;
            }
            __syncthreads();
            if (tid < 64) {
                float bt = 0.f;
                #pragma unroll
                for (int k = 0; k < 64; k++) bt += sKT[k*68 + tid] * swh[k];
                sBt[tid] = bt;
            }
            ull acc0 = 0, acc1 = 0;
            #pragma unroll
            for (int k4 = 0; k4 < 16; k4++) {
                float4 q4 = *(const float4*)&sQp[sg*68 + k4*4];
                float qa[4] = {q4.x, q4.y, q4.z, q4.w};
                #pragma unroll
                for (int kk = 0; kk < 4; kk++) {
                    float4 kv = *(const float4*)&sKT[(k4*4+kk)*68 + tg*4];
                    ull kA = pk2(kv.x, kv.y), kB = pk2(kv.z, kv.w);
                    ull qp2 = pk2(qa[kk], qa[kk]);
                    acc0 = ffma2(qp2, kA, acc0);
                    acc1 = ffma2(qp2, kB, acc1);
                }
            }
            __syncthreads();
            float2 v0 = upk2(acc0), v1 = upk2(acc1);
            int tb = tg * 4;
            sc[c*4+0] = (v0.x + sBt[tb+0]) * 0.125f;
            sc[c*4+1] = (v0.y + sBt[tb+1]) * 0.125f;
            sc[c*4+2] = (v1.x + sBt[tb+2]) * 0.125f;
            sc[c*4+3] = (v1.y + sBt[tb+3]) * 0.125f;
        }

        float mx = -1e30f;
        #pragma unroll
        for (int i = 0; i < 24; i++) mx = fmaxf(mx, sc[i]);
        #pragma unroll
        for (int o = 1; o < 16; o <<= 1) mx = fmaxf(mx, __shfl_xor_sync(0xffffffffu, mx, o));
        float sum = 0.f;
        #pragma unroll
        for (int i = 0; i < 24; i++) { sc[i] = __expf(sc[i] - mx); sum += sc[i]; }
        #pragma unroll
        for (int o = 1; o < 16; o <<= 1) sum += __shfl_xor_sync(0xffffffffu, sum, o);
        float inv = 1.0f / sum;

        #pragma unroll
        for (int c = 0; c < 6; c++) {
            float a0 = sc[c*4+0] * inv;
            float a1 = sc[c*4+1] * inv;
            float a2 = sc[c*4+2] * inv;
            float a3 = sc[c*4+3] * inv;
            int t = c*64 + tg*4;
            g_attnT[((long long)s * S + t + 0) * H + h] = a0;
            g_attnT[((long long)s * S + t + 1) * H + h] = a1;
            g_attnT[((long long)s * S + t + 2) * H + h] = a2;
            g_attnT[((long long)s * S + t + 3) * H + h] = a3;
            if (h == H - 1) {
                long long oi = (long long)OUT_MAIN + (long long)s * S + t;
                if (oi + 3 < osz)
                    *(float4*)(d_out + oi) = make_float4(a0, a1, a2, a3);
            }
        }
    } else {
        // ---- hvo2[t][h][:] = (vr @ Wvo + bvo) * (1/H) ----
        int p = b - 192;
        int n0 = (p & 7) * 64;
        int q = p >> 3;
        int h = q / 6, t0 = (q % 6) * 64;
        float* sV = sm;          // [64][65]
        float* sW = sm + 4160;   // [64][68]
        #pragma unroll
        for (int r = 0; r < 4; r++) {
            int lin = tid * 4 + r * 1024;
            int row = lin >> 6, col = lin & 63;
            float4 v4 = *(const float4*)(gv + (t0 + row) * D + h * DK + col);
            sV[row*65+col] = v4.x; sV[row*65+col+1] = v4.y;
            sV[row*65+col+2] = v4.z; sV[row*65+col+3] = v4.w;
            float4 w4 = *(const float4*)(g_Wvo + row * D + n0 + col);
            *(float4*)&sW[row*68+col] = w4;
        }
        __syncthreads();
        int tl = tid >> 2, ng = (tid & 3) * 16;
        ull acc[8];
        {
            float4 b0 = *(const float4*)(g_bvo + n0 + ng);
            float4 b1 = *(const float4*)(g_bvo + n0 + ng + 4);
            float4 b2 = *(const float4*)(g_bvo + n0 + ng + 8);
            float4 b3 = *(const float4*)(g_bvo + n0 + ng + 12);
            acc[0] = pk2(b0.x,b0.y); acc[1] = pk2(b0.z,b0.w);
            acc[2] = pk2(b1.x,b1.y); acc[3] = pk2(b1.z,b1.w);
            acc[4] = pk2(b2.x,b2.y); acc[5] = pk2(b2.z,b2.w);
            acc[6] = pk2(b3.x,b3.y); acc[7] = pk2(b3.z,b3.w);
        }
        #pragma unroll
        for (int i = 0; i < 64; i++) {
            float vv = sV[tl*65 + i];
            ull vp = pk2(vv, vv);
            const float* wr = &sW[i*68 + ng];
            acc[0] = ffma2(vp, *(const ull*)wr,        acc[0]);
            acc[1] = ffma2(vp, *(const ull*)(wr + 2),  acc[1]);
            acc[2] = ffma2(vp, *(const ull*)(wr + 4),  acc[2]);
            acc[3] = ffma2(vp, *(const ull*)(wr + 6),  acc[3]);
            acc[4] = ffma2(vp, *(const ull*)(wr + 8),  acc[4]);
            acc[5] = ffma2(vp, *(const ull*)(wr + 10), acc[5]);
            acc[6] = ffma2(vp, *(const ull*)(wr + 12), acc[6]);
            acc[7] = ffma2(vp, *(const ull*)(wr + 14), acc[7]);
        }
        int t = t0 + tl;
        #pragma unroll
        for (int rq = 0; rq < 4; rq++) {
            float2 lo = upk2(acc[rq*2]), hi = upk2(acc[rq*2+1]);
            float4 o4 = make_float4(lo.x*0.125f, lo.y*0.125f,
                                    hi.x*0.125f, hi.y*0.125f);
            *(float4*)(g_hvo2 + (t * H + h) * D + n0 + ng + rq*4) = o4;
        }
    }
}

// =================================================================
// K4: out[s,t,:] = bo + sum_h attnT[s,t,h] * hvo2[t,h,:]
// Block = (2-t tile, 96-s range). 256 thr = 128 d4 x 2 tq. 4 CTAs/SM.
// =================================================================
__global__ __launch_bounds__(256, 4) void K4(float* __restrict__ d_out,
                                             const float* __restrict__ bo,
                                             long long osz) {
    __shared__ float sA[32*2*8];   // [s][t][h] = 512 floats
    int b = blockIdx.x;
    int t0 = (b % 192) * 2;
    int s0 = (b / 192) * 96;
    int tid = threadIdx.x;
    int dl = (tid & 127) * 4, tq = tid >> 7;
    int t = t0 + tq;

    ull hp[8][2];
    #pragma unroll
    for (int hh = 0; hh < 8; hh++) {
        float4 a = *(const float4*)(g_hvo2 + (t * H + hh) * D + dl);
        hp[hh][0] = pk2(a.x, a.y); hp[hh][1] = pk2(a.z, a.w);
    }
    float4 bA = *(const float4*)(bo + dl);
    ull bop0 = pk2(bA.x, bA.y), bop1 = pk2(bA.z, bA.w);

    for (int ch = 0; ch < 3; ch++) {
        int sb = s0 + ch * 32;
        if (tid < 128) {    // stage attn [32 s][2 t][8 h] = 128 float4
            int s = tid >> 2, rem = tid & 3;
            int tt2 = rem >> 1, half = rem & 1;
            *(float4*)&sA[s*16 + tt2*8 + half*4] =
                *(const float4*)(g_attnT + ((long long)(sb+s)*S + t0+tt2)*H + half*4);
        }
        __syncthreads();
        long long oi = ((long long)sb * S + t) * D + dl;
        #pragma unroll 4
        for (int s = 0; s < 32; s++) {
            const float* wb = &sA[s*16 + tq*8];
            float4 wa = *(const float4*)wb;
            float4 wc = *(const float4*)(wb + 4);
            ull w0 = pk2(wa.x,wa.x), w1 = pk2(wa.y,wa.y);
            ull w2 = pk2(wa.z,wa.z), w3 = pk2(wa.w,wa.w);
            ull w4 = pk2(wc.x,wc.x), w5 = pk2(wc.y,wc.y);
            ull w6 = pk2(wc.z,wc.z), w7 = pk2(wc.w,wc.w);
            ull acc0 = bop0, acc1 = bop1;
            acc0 = ffma2(w0, hp[0][0], acc0); acc1 = ffma2(w0, hp[0][1], acc1);
            acc0 = ffma2(w1, hp[1][0], acc0); acc1 = ffma2(w1, hp[1][1], acc1);
            acc0 = ffma2(w2, hp[2][0], acc0); acc1 = ffma2(w2, hp[2][1], acc1);
            acc0 = ffma2(w3, hp[3][0], acc0); acc1 = ffma2(w3, hp[3][1], acc1);
            acc0 = ffma2(w4, hp[4][0], acc0); acc1 = ffma2(w4, hp[4][1], acc1);
            acc0 = ffma2(w5, hp[5][0], acc0); acc1 = ffma2(w5, hp[5][1], acc1);
            acc0 = ffma2(w6, hp[6][0], acc0); acc1 = ffma2(w6, hp[6][1], acc1);
            acc0 = ffma2(w7, hp[7][0], acc0); acc1 = ffma2(w7, hp[7][1], acc1);
            float2 r0 = upk2(acc0), r1 = upk2(acc1);
            if (oi + 3 < osz)
                __stcs((float4*)(d_out + oi), make_float4(r0.x, r0.y, r1.x, r1.y));
            oi += (long long)S * D;
        }
        __syncthreads();
    }
}

extern "C" void kernel_launch(void* const* d_in, const int* in_sizes, int n_in,
                              void* d_out, int out_size) {
    const float* x   = (const float*)d_in[0];
    const float* Wq  = (const float*)d_in[1];
    const float* bq  = (const float*)d_in[2];
    const float* Wk  = (const float*)d_in[3];
    const float* bk  = (const float*)d_in[4];
    const float* Wv  = (const float*)d_in[5];
    const float* bv  = (const float*)d_in[6];
    const float* Wqh = (const float*)d_in[7];
    const float* bqh = (const float*)d_in[8];
    const float* Wkh = (const float*)d_in[9];
    const float* Wvs = (const float*)d_in[11];
    const float* bvs = (const float*)d_in[12];
    const float* Wo  = (const float*)d_in[13];
    const float* bo  = (const float*)d_in[14];
    float* out = (float*)d_out;
    long long osz = (long long)out_size;

    K1 <<<624, 256>>>(x, Wq, bq, Wk, bk, Wv, bv, Wqh, Wkh, Wvs, bvs, bqh, Wo);
    K1r<<<641, 256>>>();
    K2 <<<576, 256>>>(out, osz);
    K4 <<<768, 256>>>(out, bo, osz);
}